// round 9
// baseline (speedup 1.0000x reference)
#include <cuda_runtime.h>
#include <math.h>

// Problem constants
#define T_TOK 16384
#define DDIM  1024
#define FDIM  4096
#define NEXP  16
#define KTOP  2
#define CAP   2560                 // ceil(K*T/E * 1.25)
#define NFLAT (T_TOK * KTOP)       // 32768
#define NB    128                  // dispatch chunks
#define CHUNK 256                  // flat entries per chunk (NB*CHUNK == NFLAT)

// -------------------- device scratch (static, no allocation) --------------------
__device__ float g_xe[NEXP * CAP * DDIM];   // dispatched tokens   [E,C,D]  160 MB
__device__ float g_h [NEXP * CAP * FDIM];   // hidden activations  [E,C,F]  640 MB
__device__ float g_ye[NEXP * CAP * DDIM];   // expert outputs      [E,C,D]  160 MB
__device__ int   g_topi[NFLAT];
__device__ float g_topv[NFLAT];
__device__ int   g_slot[NFLAT];
__device__ int   g_bh  [NB * NEXP];
__device__ int   g_boff[NB * NEXP];
__device__ int   g_count[NEXP];

// -------------------- gating: warp per token --------------------
// logits = x @ gate_w ; top-2 (ties -> lowest index, matching jax top_k);
// renormalized top-2 softmax weights computed directly from logits:
//   w0 = 1 / (1 + exp(l1 - l0)), w1 = 1 - w0   (softmax denom cancels)
__global__ void gating_kernel(const float* __restrict__ x,
                              const float* __restrict__ gw) {
    int gtid = blockIdx.x * blockDim.x + threadIdx.x;
    int t    = gtid >> 5;
    int lane = gtid & 31;
    if (t >= T_TOK) return;

    const float* xr = x + (size_t)t * DDIM;
    float acc[NEXP];
#pragma unroll
    for (int e = 0; e < NEXP; e++) acc[e] = 0.f;

    for (int d = lane; d < DDIM; d += 32) {
        float xv = __ldg(xr + d);
        const float* g = gw + d * NEXP;
#pragma unroll
        for (int e = 0; e < NEXP; e++) acc[e] += xv * __ldg(g + e);
    }
#pragma unroll
    for (int off = 16; off > 0; off >>= 1) {
#pragma unroll
        for (int e = 0; e < NEXP; e++)
            acc[e] += __shfl_xor_sync(0xffffffffu, acc[e], off);
    }
    if (lane == 0) {
        int   i0 = 0;     float v0 = acc[0];
#pragma unroll
        for (int e = 1; e < NEXP; e++)
            if (acc[e] > v0) { v0 = acc[e]; i0 = e; }
        int   i1 = -1;    float v1 = -3.0e38f;
#pragma unroll
        for (int e = 0; e < NEXP; e++)
            if (e != i0 && acc[e] > v1) { v1 = acc[e]; i1 = e; }

        float w0 = 1.0f / (1.0f + expf(v1 - v0));
        g_topi[2 * t]     = i0;
        g_topi[2 * t + 1] = i1;
        g_topv[2 * t]     = w0;
        g_topv[2 * t + 1] = 1.0f - w0;
    }
}

// -------------------- dispatch: chunk histograms --------------------
__global__ void hist_kernel() {
    __shared__ int h[NEXP];
    int tid = threadIdx.x;
    if (tid < NEXP) h[tid] = 0;
    __syncthreads();
    int i = blockIdx.x * CHUNK + tid;
    atomicAdd(&h[g_topi[i]], 1);
    __syncthreads();
    if (tid < NEXP) g_bh[blockIdx.x * NEXP + tid] = h[tid];
}

// -------------------- dispatch: per-expert exclusive scan over chunks --------------------
__global__ void scan_kernel() {
    int e = threadIdx.x;
    if (e >= NEXP) return;
    int run = 0;
#pragma unroll 8
    for (int b = 0; b < NB; b++) {
        g_boff[b * NEXP + e] = run;
        run += g_bh[b * NEXP + e];
    }
    g_count[e] = run;
}

// -------------------- dispatch: in-order rank within chunk -> slot --------------------
__global__ void rank_kernel() {
    __shared__ int se[CHUNK];
    int tid = threadIdx.x;
    int i   = blockIdx.x * CHUNK + tid;
    int e   = g_topi[i];
    se[tid] = e;
    __syncthreads();
    int r = 0;
    for (int j = 0; j < tid; j++) r += (se[j] == e);
    int loc = g_boff[blockIdx.x * NEXP + e] + r;
    g_slot[i] = (loc < CAP) ? (e * CAP + loc) : -1;
}

// -------------------- scatter token rows into per-expert buffer --------------------
__global__ void scatter_kernel(const float* __restrict__ x) {
    int i = blockIdx.x;                 // flat entry
    int s = g_slot[i];
    if (s < 0) return;
    int t = i >> 1;
    const float4* src = (const float4*)(x + (size_t)t * DDIM);
    float4*       dst = (float4*)(g_xe + (size_t)s * DDIM);
    int tid = threadIdx.x;              // 128 threads, 256 float4 per row
    dst[tid]       = src[tid];
    dst[tid + 128] = src[tid + 128];
}

// -------------------- gelu (tanh approximation, JAX default) --------------------
__device__ __forceinline__ float gelu_f(float v) {
    float u = 0.7978845608028654f * (v + 0.044715f * v * v * v);
    return 0.5f * v * (1.0f + tanhf(u));
}

// -------------------- batched per-expert SGEMM --------------------
// MODE 0: h  = gelu(xe @ w1 + b1)   A=g_xe [C,1024], B=w1[e] [1024,4096]
// MODE 1: ye =       h @ w2 + b2    A=g_h  [C,4096], B=w2[e] [4096,1024]
// Tile 128x128, BK=16, 256 threads, 8x8 per-thread microtile.
// Early-exit row tiles entirely above the expert's used count.
template <int MODE>
__global__ __launch_bounds__(256, 2)
void gemm_kernel(const float* __restrict__ Ball,
                 const float* __restrict__ biasAll) {
    constexpr int Kdim  = (MODE == 0) ? DDIM : FDIM;
    constexpr int Ncols = (MODE == 0) ? FDIM : DDIM;

    int e   = blockIdx.z;
    int cnt = min(g_count[e], CAP);
    int m0  = blockIdx.y * 128;
    if (m0 >= cnt) return;
    int n0  = blockIdx.x * 128;

    const float* Aall = (MODE == 0) ? g_xe : g_h;
    float*       Oall = (MODE == 0) ? g_h  : g_ye;

    const float* A   = Aall + (size_t)e * CAP * Kdim;
    const float* B   = Ball + (size_t)e * Kdim * Ncols;
    float*       Out = Oall + (size_t)e * CAP * Ncols;

    __shared__ float As[16][128];   // transposed: As[k][m]
    __shared__ float Bs[16][128];   // Bs[k][n]

    int tid = threadIdx.x;
    int tx  = tid & 15;
    int ty  = tid >> 4;

    float acc[8][8];
#pragma unroll
    for (int i = 0; i < 8; i++)
#pragma unroll
        for (int j = 0; j < 8; j++) acc[i][j] = 0.f;

    for (int k0 = 0; k0 < Kdim; k0 += 16) {
        // A tile: 128 rows x 16 cols  (512 float4)
#pragma unroll
        for (int it = 0; it < 2; it++) {
            int idx = tid + 256 * it;
            int r   = idx >> 2;          // 0..127
            int c   = (idx & 3) << 2;    // 0,4,8,12
            float4 v = *(const float4*)(A + (size_t)(m0 + r) * Kdim + k0 + c);
            As[c + 0][r] = v.x;
            As[c + 1][r] = v.y;
            As[c + 2][r] = v.z;
            As[c + 3][r] = v.w;
        }
        // B tile: 16 rows x 128 cols (512 float4, fully coalesced)
#pragma unroll
        for (int it = 0; it < 2; it++) {
            int idx = tid + 256 * it;
            int r   = idx >> 5;          // 0..15
            int c   = (idx & 31) << 2;   // 0..124
            *(float4*)(&Bs[r][c]) =
                *(const float4*)(B + (size_t)(k0 + r) * Ncols + n0 + c);
        }
        __syncthreads();

#pragma unroll
        for (int kk = 0; kk < 16; kk++) {
            float a[8], b[8];
            *(float4*)(a)     = *(const float4*)(&As[kk][ty * 8]);
            *(float4*)(a + 4) = *(const float4*)(&As[kk][ty * 8 + 4]);
            *(float4*)(b)     = *(const float4*)(&Bs[kk][tx * 8]);
            *(float4*)(b + 4) = *(const float4*)(&Bs[kk][tx * 8 + 4]);
#pragma unroll
            for (int i = 0; i < 8; i++)
#pragma unroll
                for (int j = 0; j < 8; j++)
                    acc[i][j] += a[i] * b[j];
        }
        __syncthreads();
    }

    // epilogue: + bias, optional gelu, vectorized store
    const float* bias = biasAll + (size_t)e * Ncols + n0 + tx * 8;
    float bv[8];
#pragma unroll
    for (int j = 0; j < 8; j++) bv[j] = bias[j];

#pragma unroll
    for (int i = 0; i < 8; i++) {
        int m = m0 + ty * 8 + i;
        float vv[8];
#pragma unroll
        for (int j = 0; j < 8; j++) {
            float v = acc[i][j] + bv[j];
            vv[j] = (MODE == 0) ? gelu_f(v) : v;
        }
        float* orow = Out + (size_t)m * Ncols + n0 + tx * 8;
        *(float4*)(orow)     = make_float4(vv[0], vv[1], vv[2], vv[3]);
        *(float4*)(orow + 4) = make_float4(vv[4], vv[5], vv[6], vv[7]);
    }
}

// -------------------- combine: gate-weighted sum over K=2 slots --------------------
__global__ void combine_kernel(float* __restrict__ out) {
    int t   = blockIdx.x;
    int tid = threadIdx.x;              // 256 threads, 1 float4 each
    int   s0 = g_slot[2 * t];
    int   s1 = g_slot[2 * t + 1];
    float w0 = g_topv[2 * t];
    float w1 = g_topv[2 * t + 1];

    float4 r = make_float4(0.f, 0.f, 0.f, 0.f);
    if (s0 >= 0) {
        float4 y = *(const float4*)(g_ye + (size_t)s0 * DDIM + tid * 4);
        r.x += w0 * y.x; r.y += w0 * y.y; r.z += w0 * y.z; r.w += w0 * y.w;
    }
    if (s1 >= 0) {
        float4 y = *(const float4*)(g_ye + (size_t)s1 * DDIM + tid * 4);
        r.x += w1 * y.x; r.y += w1 * y.y; r.z += w1 * y.z; r.w += w1 * y.w;
    }
    *(float4*)(out + (size_t)t * DDIM + tid * 4) = r;
}

// -------------------- launch --------------------
extern "C" void kernel_launch(void* const* d_in, const int* in_sizes, int n_in,
                              void* d_out, int out_size) {
    const float* x  = (const float*)d_in[0];   // [T, D]
    const float* gw = (const float*)d_in[1];   // [D, E]
    const float* w1 = (const float*)d_in[2];   // [E, D, F]
    const float* b1 = (const float*)d_in[3];   // [E, F]
    const float* w2 = (const float*)d_in[4];   // [E, F, D]
    const float* b2 = (const float*)d_in[5];   // [E, D]
    float* out = (float*)d_out;                // [T, D]

    gating_kernel<<<T_TOK / 8, 256>>>(x, gw);
    hist_kernel<<<NB, CHUNK>>>();
    scan_kernel<<<1, 32>>>();
    rank_kernel<<<NB, CHUNK>>>();
    scatter_kernel<<<NFLAT, 128>>>(x);

    gemm_kernel<0><<<dim3(FDIM / 128, CAP / 128, NEXP), 256>>>(w1, b1);
    gemm_kernel<1><<<dim3(DDIM / 128, CAP / 128, NEXP), 256>>>(w2, b2);

    combine_kernel<<<T_TOK, 256>>>(out);
}

// round 13
// speedup vs baseline: 2.0247x; 2.0247x over previous
#include <cuda_runtime.h>
#include <cuda_bf16.h>
#include <math.h>
#include <stdint.h>

// ---------------- problem constants ----------------
#define T_TOK 16384
#define DDIM  1024
#define FDIM  4096
#define NEXP  16
#define KTOP  2
#define CAP   2560
#define NFLAT (T_TOK * KTOP)
#define NB    128
#define CHUNK 256

// ---------------- GEMM tiling ----------------
#define BM 128
#define BN 128
#define BK 32
#define STAGE_A (BM * BK * 2)          // 8192 B
#define STAGE_B (BN * BK * 2)          // 8192 B

// ---------------- device scratch (static, zero-initialized) ----------------
__device__ __nv_bfloat16 g_xe_hi[NEXP * CAP * DDIM];
__device__ __nv_bfloat16 g_xe_lo[NEXP * CAP * DDIM];
__device__ __nv_bfloat16 g_h_hi [NEXP * CAP * FDIM];
__device__ __nv_bfloat16 g_h_lo [NEXP * CAP * FDIM];
__device__ float         g_ye   [NEXP * CAP * DDIM];
__device__ __nv_bfloat16 g_wt1_hi[NEXP * FDIM * DDIM];   // w1^T: [E][F][D] (K=D contiguous)
__device__ __nv_bfloat16 g_wt1_lo[NEXP * FDIM * DDIM];
__device__ __nv_bfloat16 g_wt2_hi[NEXP * DDIM * FDIM];   // w2^T: [E][D][F] (K=F contiguous)
__device__ __nv_bfloat16 g_wt2_lo[NEXP * DDIM * FDIM];
__device__ int   g_topi[NFLAT];
__device__ float g_topv[NFLAT];
__device__ int   g_slot[NFLAT];
__device__ int   g_bh  [NB * NEXP];
__device__ int   g_boff[NB * NEXP];
__device__ int   g_count[NEXP];

// ---------------- low-level helpers ----------------
__device__ __forceinline__ uint32_t smem_u32(const void* p) {
    uint32_t a;
    asm("{ .reg .u64 t; cvta.to.shared.u64 t, %1; cvt.u32.u64 %0, t; }" : "=r"(a) : "l"(p));
    return a;
}

__device__ __forceinline__ void ldsm_x4(uint32_t& r0, uint32_t& r1, uint32_t& r2, uint32_t& r3,
                                        uint32_t addr) {
    asm volatile("ldmatrix.sync.aligned.m8n8.x4.shared.b16 {%0,%1,%2,%3}, [%4];"
                 : "=r"(r0), "=r"(r1), "=r"(r2), "=r"(r3) : "r"(addr));
}

__device__ __forceinline__ void mma16816(float* d, const uint32_t* a, const uint32_t* b) {
    asm volatile("mma.sync.aligned.m16n8k16.row.col.f32.bf16.bf16.f32 "
                 "{%0,%1,%2,%3}, {%4,%5,%6,%7}, {%8,%9}, {%0,%1,%2,%3};"
                 : "+f"(d[0]), "+f"(d[1]), "+f"(d[2]), "+f"(d[3])
                 : "r"(a[0]), "r"(a[1]), "r"(a[2]), "r"(a[3]), "r"(b[0]), "r"(b[1]));
}

// hi/lo bf16 split
__device__ __forceinline__ void split1(float v, unsigned short& h, unsigned short& l) {
    __nv_bfloat16 hb = __float2bfloat16(v);
    float r = v - __bfloat162float(hb);
    __nv_bfloat16 lb = __float2bfloat16(r);
    h = __bfloat16_as_ushort(hb);
    l = __bfloat16_as_ushort(lb);
}

// ---------------- gating: warp per token ----------------
__global__ void gating_kernel(const float* __restrict__ x,
                              const float* __restrict__ gw) {
    int gtid = blockIdx.x * blockDim.x + threadIdx.x;
    int t    = gtid >> 5;
    int lane = gtid & 31;
    if (t >= T_TOK) return;

    const float* xr = x + (size_t)t * DDIM;
    float acc[NEXP];
#pragma unroll
    for (int e = 0; e < NEXP; e++) acc[e] = 0.f;
    for (int d = lane; d < DDIM; d += 32) {
        float xv = __ldg(xr + d);
        const float* g = gw + d * NEXP;
#pragma unroll
        for (int e = 0; e < NEXP; e++) acc[e] += xv * __ldg(g + e);
    }
#pragma unroll
    for (int off = 16; off > 0; off >>= 1)
#pragma unroll
        for (int e = 0; e < NEXP; e++)
            acc[e] += __shfl_xor_sync(0xffffffffu, acc[e], off);
    if (lane == 0) {
        int i0 = 0; float v0 = acc[0];
#pragma unroll
        for (int e = 1; e < NEXP; e++) if (acc[e] > v0) { v0 = acc[e]; i0 = e; }
        int i1 = -1; float v1 = -3.0e38f;
#pragma unroll
        for (int e = 0; e < NEXP; e++) if (e != i0 && acc[e] > v1) { v1 = acc[e]; i1 = e; }
        float w0 = 1.0f / (1.0f + expf(v1 - v0));
        g_topi[2 * t] = i0;  g_topi[2 * t + 1] = i1;
        g_topv[2 * t] = w0;  g_topv[2 * t + 1] = 1.0f - w0;
    }
}

// ---------------- dispatch chain (proven) ----------------
__global__ void hist_kernel() {
    __shared__ int h[NEXP];
    int tid = threadIdx.x;
    if (tid < NEXP) h[tid] = 0;
    __syncthreads();
    atomicAdd(&h[g_topi[blockIdx.x * CHUNK + tid]], 1);
    __syncthreads();
    if (tid < NEXP) g_bh[blockIdx.x * NEXP + tid] = h[tid];
}

__global__ void scan_kernel() {
    int e = threadIdx.x;
    if (e >= NEXP) return;
    int run = 0;
#pragma unroll 8
    for (int b = 0; b < NB; b++) { g_boff[b * NEXP + e] = run; run += g_bh[b * NEXP + e]; }
    g_count[e] = run;
}

__global__ void rank_kernel() {
    __shared__ int se[CHUNK];
    int tid = threadIdx.x;
    int i   = blockIdx.x * CHUNK + tid;
    int e   = g_topi[i];
    se[tid] = e;
    __syncthreads();
    int r = 0;
    for (int j = 0; j < tid; j++) r += (se[j] == e);
    int loc = g_boff[blockIdx.x * NEXP + e] + r;
    g_slot[i] = (loc < CAP) ? (e * CAP + loc) : -1;
}

// ---------------- scatter with bf16 hi/lo split ----------------
__global__ void scatter_split(const float* __restrict__ x) {
    int i = blockIdx.x;
    int s = g_slot[i];
    if (s < 0) return;
    int t = i >> 1;
    int tid = threadIdx.x;                        // 128 threads, 8 floats each
    const float* src = x + (size_t)t * DDIM + tid * 8;
    float v[8];
    *(float4*)(v)     = *(const float4*)(src);
    *(float4*)(v + 4) = *(const float4*)(src + 4);
    unsigned short h[8], l[8];
#pragma unroll
    for (int j = 0; j < 8; j++) split1(v[j], h[j], l[j]);
    ((uint4*)(g_xe_hi + (size_t)s * DDIM))[tid] = *(const uint4*)h;
    ((uint4*)(g_xe_lo + (size_t)s * DDIM))[tid] = *(const uint4*)l;
}

// ---------------- weight transpose + split ----------------
// FIX (R13): output arrays are __device__ globals referenced from DEVICE code.
// Previously they were passed as host-side kernel arguments; naming a __device__
// symbol in host code yields the host shadow address, and with GB300 ATS the
// device writes landed silently in host memory, leaving g_wt* all zero.
// WHICH=1: w1 [E,D,F] -> g_wt1 [E,F,D];  WHICH=2: w2 [E,F,D] -> g_wt2 [E,D,F]
template <int R, int Cc, int WHICH>
__global__ void transpose_split(const float* __restrict__ in) {
    __nv_bfloat16* oh = (WHICH == 1) ? g_wt1_hi : g_wt2_hi;
    __nv_bfloat16* ol = (WHICH == 1) ? g_wt1_lo : g_wt2_lo;
    __shared__ float tile[32][33];
    int c0 = blockIdx.x * 32, r0 = blockIdx.y * 32, e = blockIdx.z;
    int tx = threadIdx.x, ty = threadIdx.y;
    const float* ip = in + (size_t)e * R * Cc;
#pragma unroll
    for (int i = 0; i < 4; i++)
        tile[ty + 8 * i][tx] = ip[(size_t)(r0 + ty + 8 * i) * Cc + c0 + tx];
    __syncthreads();
    size_t ob = (size_t)e * R * Cc;
#pragma unroll
    for (int i = 0; i < 4; i++) {
        float v = tile[tx][ty + 8 * i];
        unsigned short h, l;
        split1(v, h, l);
        size_t o = ob + (size_t)(c0 + ty + 8 * i) * R + r0 + tx;
        oh[o] = __ushort_as_bfloat16(h);
        ol[o] = __ushort_as_bfloat16(l);
    }
}

// ---------------- gelu (tanh approx, JAX default) ----------------
__device__ __forceinline__ float gelu_f(float v) {
    float u = 0.7978845608028654f * (v + 0.044715f * v * v * v);
    return 0.5f * v * (1.0f + tanhf(u));
}

// ---------------- tensor-core GEMM: logical K' = 3*KDIM (bf16x3 split) ------------------
// MODE 0: h  = gelu(xe @ w1 + b1) -> h hi/lo bf16   (KDIM=1024, NTOT=4096)
// MODE 1: ye =       h @ w2 + b2  -> ye fp32        (KDIM=4096, NTOT=1024)
// A regions: [hi | lo | hi], B regions: [hi | hi | lo]  => Ah*Bh + Al*Bh + Ah*Bl
template <int KDIM, int NTOT, int MODE>
__global__ __launch_bounds__(256)
void mma_gemm(const float* __restrict__ bias) {
    int e   = blockIdx.z;
    int cnt = min(g_count[e], CAP);
    int m0  = blockIdx.y * BM;
    if (m0 >= cnt) return;
    int n0  = blockIdx.x * BN;

    __shared__ __align__(16) char sm[STAGE_A + STAGE_B];
    uint32_t sA = smem_u32(sm);
    uint32_t sB = sA + STAGE_A;

    const __nv_bfloat16 *Ah, *Al, *Bh, *Bl;
    if (MODE == 0) { Ah = g_xe_hi; Al = g_xe_lo; Bh = g_wt1_hi; Bl = g_wt1_lo; }
    else           { Ah = g_h_hi;  Al = g_h_lo;  Bh = g_wt2_hi; Bl = g_wt2_lo; }
    const __nv_bfloat16* Areg[3] = { Ah, Al, Ah };
    const __nv_bfloat16* Breg[3] = { Bh, Bh, Bl };

    size_t aBase = (size_t)e * CAP  * KDIM + (size_t)m0 * KDIM;
    size_t bBase = (size_t)e * NTOT * KDIM + (size_t)n0 * KDIM;

    int tid  = threadIdx.x;
    int lane = tid & 31;
    int wid  = tid >> 5;
    int wm   = (wid & 3) * 32;     // warp M offset (4 warps in M)
    int wn   = (wid >> 2) * 64;    // warp N offset (2 warps in N)

    // ---- loader mapping: thread -> rows (r0, r0+64), 16B col c0 ----
    int r0 = tid >> 2, c0 = tid & 3;
    int r1 = r0 + 64;
    uint32_t swz0 = (uint32_t)(r0 * 64 + ((c0 ^ ((r0 >> 1) & 3)) << 4));
    uint32_t swz1 = (uint32_t)(r1 * 64 + ((c0 ^ ((r1 >> 1) & 3)) << 4));
    size_t goff0 = (size_t)r0 * KDIM + c0 * 8;
    size_t goff1 = (size_t)r1 * KDIM + c0 * 8;

    // ---- per-lane ldmatrix offsets (ks=0); ks=1 XORs byte 32 -> k+16 ----
    int gq = lane >> 3;
    int ri = lane & 7;
    int a_r = ri + ((gq & 1) << 3);
    int a_c = (gq >> 1);
    uint32_t aoff[2];
#pragma unroll
    for (int mt = 0; mt < 2; mt++) {
        int m = wm + mt * 16 + a_r;
        aoff[mt] = (uint32_t)(m * 64 + ((a_c ^ ((m >> 1) & 3)) << 4));
    }
    int b_r = ri + ((gq >> 1) << 3);
    int b_c = (gq & 1);
    uint32_t boff[4];
#pragma unroll
    for (int bt = 0; bt < 4; bt++) {
        int n = wn + bt * 16 + b_r;
        boff[bt] = (uint32_t)(n * 64 + ((b_c ^ ((n >> 1) & 3)) << 4));
    }

    constexpr int KCH = KDIM / BK;
    constexpr int TCH = 3 * KCH;

    float acc[2][8][4];
#pragma unroll
    for (int mt = 0; mt < 2; mt++)
#pragma unroll
        for (int nt = 0; nt < 8; nt++)
#pragma unroll
            for (int q = 0; q < 4; q++) acc[mt][nt][q] = 0.f;

    // prefetch chunk 0 into registers
    uint4 pa0, pa1, pb0, pb1;
    {
        const __nv_bfloat16* Ag = Areg[0] + aBase;
        const __nv_bfloat16* Bg = Breg[0] + bBase;
        pa0 = *(const uint4*)(Ag + goff0);
        pa1 = *(const uint4*)(Ag + goff1);
        pb0 = *(const uint4*)(Bg + goff0);
        pb1 = *(const uint4*)(Bg + goff1);
    }

    for (int t = 0; t < TCH; t++) {
        __syncthreads();                 // previous compute done reading smem
        *(uint4*)(sm + swz0)           = pa0;
        *(uint4*)(sm + swz1)           = pa1;
        *(uint4*)(sm + STAGE_A + swz0) = pb0;
        *(uint4*)(sm + STAGE_A + swz1) = pb1;
        __syncthreads();                 // smem chunk t ready

        // prefetch chunk t+1 (LDG overlaps the compute below)
        int tn = t + 1;
        if (tn < TCH) {
            int reg = tn / KCH;
            int k0  = (tn - reg * KCH) * BK;
            const __nv_bfloat16* Ag = Areg[reg] + aBase + k0;
            const __nv_bfloat16* Bg = Breg[reg] + bBase + k0;
            pa0 = *(const uint4*)(Ag + goff0);
            pa1 = *(const uint4*)(Ag + goff1);
            pb0 = *(const uint4*)(Bg + goff0);
            pb1 = *(const uint4*)(Bg + goff1);
        }

#pragma unroll
        for (int ks = 0; ks < 2; ks++) {
            uint32_t kx = ks << 5;
            uint32_t a[2][4];
            ldsm_x4(a[0][0], a[0][1], a[0][2], a[0][3], sA + (aoff[0] ^ kx));
            ldsm_x4(a[1][0], a[1][1], a[1][2], a[1][3], sA + (aoff[1] ^ kx));
            uint32_t b[4][4];
#pragma unroll
            for (int bt = 0; bt < 4; bt++)
                ldsm_x4(b[bt][0], b[bt][1], b[bt][2], b[bt][3], sB + (boff[bt] ^ kx));
#pragma unroll
            for (int mt = 0; mt < 2; mt++)
#pragma unroll
                for (int nt = 0; nt < 8; nt++)
                    mma16816(acc[mt][nt], a[mt], &b[nt >> 1][(nt & 1) * 2]);
        }
    }

    // ---- epilogue ----
    int lrow = lane >> 2;
    int lcol = (lane & 3) * 2;
#pragma unroll
    for (int mt = 0; mt < 2; mt++) {
#pragma unroll
        for (int hh = 0; hh < 2; hh++) {
            int m = m0 + wm + mt * 16 + lrow + 8 * hh;
            size_t rb = ((size_t)e * CAP + m) * (size_t)NTOT;
#pragma unroll
            for (int nt = 0; nt < 8; nt++) {
                int cg = n0 + wn + nt * 8 + lcol;
                float2 bv = *(const float2*)(bias + (size_t)e * NTOT + cg);
                float v0 = acc[mt][nt][2 * hh]     + bv.x;
                float v1 = acc[mt][nt][2 * hh + 1] + bv.y;
                if (MODE == 0) {
                    v0 = gelu_f(v0);
                    v1 = gelu_f(v1);
                    unsigned short h0, l0, h1, l1;
                    split1(v0, h0, l0);
                    split1(v1, h1, l1);
                    *(uint32_t*)(g_h_hi + rb + cg) = (uint32_t)h0 | ((uint32_t)h1 << 16);
                    *(uint32_t*)(g_h_lo + rb + cg) = (uint32_t)l0 | ((uint32_t)l1 << 16);
                } else {
                    float2 o; o.x = v0; o.y = v1;
                    *(float2*)(g_ye + rb + cg) = o;
                }
            }
        }
    }
}

// ---------------- combine: gate-weighted sum over K=2 slots ----------------
__global__ void combine_kernel(float* __restrict__ out) {
    int t   = blockIdx.x;
    int tid = threadIdx.x;
    int   s0 = g_slot[2 * t];
    int   s1 = g_slot[2 * t + 1];
    float w0 = g_topv[2 * t];
    float w1 = g_topv[2 * t + 1];
    float4 r = make_float4(0.f, 0.f, 0.f, 0.f);
    if (s0 >= 0) {
        float4 y = *(const float4*)(g_ye + (size_t)s0 * DDIM + tid * 4);
        r.x += w0 * y.x; r.y += w0 * y.y; r.z += w0 * y.z; r.w += w0 * y.w;
    }
    if (s1 >= 0) {
        float4 y = *(const float4*)(g_ye + (size_t)s1 * DDIM + tid * 4);
        r.x += w1 * y.x; r.y += w1 * y.y; r.z += w1 * y.z; r.w += w1 * y.w;
    }
    *(float4*)(out + (size_t)t * DDIM + tid * 4) = r;
}

// ---------------- launch ----------------
extern "C" void kernel_launch(void* const* d_in, const int* in_sizes, int n_in,
                              void* d_out, int out_size) {
    const float* x  = (const float*)d_in[0];
    const float* gw = (const float*)d_in[1];
    const float* w1 = (const float*)d_in[2];
    const float* b1 = (const float*)d_in[3];
    const float* w2 = (const float*)d_in[4];
    const float* b2 = (const float*)d_in[5];
    float* out = (float*)d_out;

    // weight prep: w1 [E,D,F] -> g_wt1 [E,F,D]; w2 [E,F,D] -> g_wt2 [E,D,F]
    transpose_split<DDIM, FDIM, 1><<<dim3(FDIM / 32, DDIM / 32, NEXP), dim3(32, 8)>>>(w1);
    transpose_split<FDIM, DDIM, 2><<<dim3(DDIM / 32, FDIM / 32, NEXP), dim3(32, 8)>>>(w2);

    gating_kernel<<<T_TOK / 8, 256>>>(x, gw);
    hist_kernel<<<NB, CHUNK>>>();
    scan_kernel<<<1, 32>>>();
    rank_kernel<<<NB, CHUNK>>>();
    scatter_split<<<NFLAT, 128>>>(x);

    mma_gemm<DDIM, FDIM, 0><<<dim3(FDIM / BN, CAP / BM, NEXP), 256>>>(b1);
    mma_gemm<FDIM, DDIM, 1><<<dim3(DDIM / BN, CAP / BM, NEXP), 256>>>(b2);

    combine_kernel<<<T_TOK, 256>>>(out);
}

// round 14
// speedup vs baseline: 2.2835x; 1.1278x over previous
#include <cuda_runtime.h>
#include <cuda_bf16.h>
#include <math.h>
#include <stdint.h>

// ---------------- problem constants ----------------
#define T_TOK 16384
#define DDIM  1024
#define FDIM  4096
#define NEXP  16
#define KTOP  2
#define CAP   2560
#define NFLAT (T_TOK * KTOP)
#define NB    128
#define CHUNK 256

// ---------------- GEMM tiling ----------------
#define BM 128
#define BN 128
#define BK 32
#define STAGES 3
#define STAGE_A (BM * BK * 2)          // 8192 B
#define STAGE_B (BN * BK * 2)          // 8192 B
#define STAGE_SZ (STAGE_A + STAGE_B)   // 16384 B  -> 3 stages = 48 KB static smem

// ---------------- device scratch (static, zero-initialized) ----------------
__device__ __nv_bfloat16 g_xe_hi[NEXP * CAP * DDIM];
__device__ __nv_bfloat16 g_xe_lo[NEXP * CAP * DDIM];
__device__ __nv_bfloat16 g_h_hi [NEXP * CAP * FDIM];
__device__ __nv_bfloat16 g_h_lo [NEXP * CAP * FDIM];
__device__ float         g_ye   [NEXP * CAP * DDIM];
__device__ __nv_bfloat16 g_wt1_hi[NEXP * FDIM * DDIM];   // w1^T: [E][F][D] (K=D contiguous)
__device__ __nv_bfloat16 g_wt1_lo[NEXP * FDIM * DDIM];
__device__ __nv_bfloat16 g_wt2_hi[NEXP * DDIM * FDIM];   // w2^T: [E][D][F] (K=F contiguous)
__device__ __nv_bfloat16 g_wt2_lo[NEXP * DDIM * FDIM];
__device__ int   g_topi[NFLAT];
__device__ float g_topv[NFLAT];
__device__ int   g_slot[NFLAT];
__device__ int   g_bh  [NB * NEXP];
__device__ int   g_boff[NB * NEXP];
__device__ int   g_count[NEXP];

// ---------------- low-level helpers ----------------
__device__ __forceinline__ uint32_t smem_u32(const void* p) {
    uint32_t a;
    asm("{ .reg .u64 t; cvta.to.shared.u64 t, %1; cvt.u32.u64 %0, t; }" : "=r"(a) : "l"(p));
    return a;
}

__device__ __forceinline__ void cp_async16(uint32_t dst, const void* src) {
    asm volatile("cp.async.cg.shared.global [%0], [%1], 16;"
                 :: "r"(dst), "l"(__cvta_generic_to_global(src)) : "memory");
}
#define CP_COMMIT() asm volatile("cp.async.commit_group;" ::: "memory")
#define CP_WAIT_1() asm volatile("cp.async.wait_group 1;" ::: "memory")

__device__ __forceinline__ void ldsm_x4(uint32_t& r0, uint32_t& r1, uint32_t& r2, uint32_t& r3,
                                        uint32_t addr) {
    asm volatile("ldmatrix.sync.aligned.m8n8.x4.shared.b16 {%0,%1,%2,%3}, [%4];"
                 : "=r"(r0), "=r"(r1), "=r"(r2), "=r"(r3) : "r"(addr));
}

__device__ __forceinline__ void mma16816(float* d, const uint32_t* a, const uint32_t* b) {
    asm volatile("mma.sync.aligned.m16n8k16.row.col.f32.bf16.bf16.f32 "
                 "{%0,%1,%2,%3}, {%4,%5,%6,%7}, {%8,%9}, {%0,%1,%2,%3};"
                 : "+f"(d[0]), "+f"(d[1]), "+f"(d[2]), "+f"(d[3])
                 : "r"(a[0]), "r"(a[1]), "r"(a[2]), "r"(a[3]), "r"(b[0]), "r"(b[1]));
}

// hi/lo bf16 split
__device__ __forceinline__ void split1(float v, unsigned short& h, unsigned short& l) {
    __nv_bfloat16 hb = __float2bfloat16(v);
    float r = v - __bfloat162float(hb);
    __nv_bfloat16 lb = __float2bfloat16(r);
    h = __bfloat16_as_ushort(hb);
    l = __bfloat16_as_ushort(lb);
}

// ---------------- gating: warp per token ----------------
__global__ void gating_kernel(const float* __restrict__ x,
                              const float* __restrict__ gw) {
    int gtid = blockIdx.x * blockDim.x + threadIdx.x;
    int t    = gtid >> 5;
    int lane = gtid & 31;
    if (t >= T_TOK) return;

    const float* xr = x + (size_t)t * DDIM;
    float acc[NEXP];
#pragma unroll
    for (int e = 0; e < NEXP; e++) acc[e] = 0.f;
    for (int d = lane; d < DDIM; d += 32) {
        float xv = __ldg(xr + d);
        const float* g = gw + d * NEXP;
#pragma unroll
        for (int e = 0; e < NEXP; e++) acc[e] += xv * __ldg(g + e);
    }
#pragma unroll
    for (int off = 16; off > 0; off >>= 1)
#pragma unroll
        for (int e = 0; e < NEXP; e++)
            acc[e] += __shfl_xor_sync(0xffffffffu, acc[e], off);
    if (lane == 0) {
        int i0 = 0; float v0 = acc[0];
#pragma unroll
        for (int e = 1; e < NEXP; e++) if (acc[e] > v0) { v0 = acc[e]; i0 = e; }
        int i1 = -1; float v1 = -3.0e38f;
#pragma unroll
        for (int e = 0; e < NEXP; e++) if (e != i0 && acc[e] > v1) { v1 = acc[e]; i1 = e; }
        float w0 = 1.0f / (1.0f + expf(v1 - v0));
        g_topi[2 * t] = i0;  g_topi[2 * t + 1] = i1;
        g_topv[2 * t] = w0;  g_topv[2 * t + 1] = 1.0f - w0;
    }
}

// ---------------- dispatch chain (proven) ----------------
__global__ void hist_kernel() {
    __shared__ int h[NEXP];
    int tid = threadIdx.x;
    if (tid < NEXP) h[tid] = 0;
    __syncthreads();
    atomicAdd(&h[g_topi[blockIdx.x * CHUNK + tid]], 1);
    __syncthreads();
    if (tid < NEXP) g_bh[blockIdx.x * NEXP + tid] = h[tid];
}

__global__ void scan_kernel() {
    int e = threadIdx.x;
    if (e >= NEXP) return;
    int run = 0;
#pragma unroll 8
    for (int b = 0; b < NB; b++) { g_boff[b * NEXP + e] = run; run += g_bh[b * NEXP + e]; }
    g_count[e] = run;
}

__global__ void rank_kernel() {
    __shared__ int se[CHUNK];
    int tid = threadIdx.x;
    int i   = blockIdx.x * CHUNK + tid;
    int e   = g_topi[i];
    se[tid] = e;
    __syncthreads();
    int r = 0;
    for (int j = 0; j < tid; j++) r += (se[j] == e);
    int loc = g_boff[blockIdx.x * NEXP + e] + r;
    g_slot[i] = (loc < CAP) ? (e * CAP + loc) : -1;
}

// ---------------- scatter with bf16 hi/lo split ----------------
__global__ void scatter_split(const float* __restrict__ x) {
    int i = blockIdx.x;
    int s = g_slot[i];
    if (s < 0) return;
    int t = i >> 1;
    int tid = threadIdx.x;                        // 128 threads, 8 floats each
    const float* src = x + (size_t)t * DDIM + tid * 8;
    float v[8];
    *(float4*)(v)     = *(const float4*)(src);
    *(float4*)(v + 4) = *(const float4*)(src + 4);
    unsigned short h[8], l[8];
#pragma unroll
    for (int j = 0; j < 8; j++) split1(v[j], h[j], l[j]);
    ((uint4*)(g_xe_hi + (size_t)s * DDIM))[tid] = *(const uint4*)h;
    ((uint4*)(g_xe_lo + (size_t)s * DDIM))[tid] = *(const uint4*)l;
}

// ---------------- weight transpose + split ----------------
// Output arrays are __device__ globals referenced from DEVICE code (R13 fix:
// passing them as host-side args yields the host shadow symbol; with GB300 ATS
// the writes land silently in host memory).
// WHICH=1: w1 [E,D,F] -> g_wt1 [E,F,D];  WHICH=2: w2 [E,F,D] -> g_wt2 [E,D,F]
template <int R, int Cc, int WHICH>
__global__ void transpose_split(const float* __restrict__ in) {
    __nv_bfloat16* oh = (WHICH == 1) ? g_wt1_hi : g_wt2_hi;
    __nv_bfloat16* ol = (WHICH == 1) ? g_wt1_lo : g_wt2_lo;
    __shared__ float tile[32][33];
    int c0 = blockIdx.x * 32, r0 = blockIdx.y * 32, e = blockIdx.z;
    int tx = threadIdx.x, ty = threadIdx.y;
    const float* ip = in + (size_t)e * R * Cc;
#pragma unroll
    for (int i = 0; i < 4; i++)
        tile[ty + 8 * i][tx] = ip[(size_t)(r0 + ty + 8 * i) * Cc + c0 + tx];
    __syncthreads();
    size_t ob = (size_t)e * R * Cc;
#pragma unroll
    for (int i = 0; i < 4; i++) {
        float v = tile[tx][ty + 8 * i];
        unsigned short h, l;
        split1(v, h, l);
        size_t o = ob + (size_t)(c0 + ty + 8 * i) * R + r0 + tx;
        oh[o] = __ushort_as_bfloat16(h);
        ol[o] = __ushort_as_bfloat16(l);
    }
}

// ---------------- gelu (tanh approx, JAX default) ----------------
__device__ __forceinline__ float gelu_f(float v) {
    float u = 0.7978845608028654f * (v + 0.044715f * v * v * v);
    return 0.5f * v * (1.0f + tanhf(u));
}

// ---------------- tensor-core GEMM: logical K' = 3*KDIM (bf16x3 split) ------------------
// MODE 0: h  = gelu(xe @ w1 + b1) -> h hi/lo bf16   (KDIM=1024, NTOT=4096)
// MODE 1: ye =       h @ w2 + b2  -> ye fp32        (KDIM=4096, NTOT=1024)
// A regions: [hi | lo | hi], B regions: [hi | hi | lo]  => Ah*Bh + Al*Bh + Ah*Bl
// Mainloop: 3-stage cp.async pipeline (wait_group 1 -> barrier -> issue t+2 -> compute t)
template <int KDIM, int NTOT, int MODE>
__global__ __launch_bounds__(256)
void mma_gemm(const float* __restrict__ bias) {
    int e   = blockIdx.z;
    int cnt = min(g_count[e], CAP);
    int m0  = blockIdx.y * BM;
    if (m0 >= cnt) return;
    int n0  = blockIdx.x * BN;

    __shared__ __align__(16) char sm[STAGES * STAGE_SZ];
    uint32_t smb = smem_u32(sm);

    const __nv_bfloat16 *Ah, *Al, *Bh, *Bl;
    if (MODE == 0) { Ah = g_xe_hi; Al = g_xe_lo; Bh = g_wt1_hi; Bl = g_wt1_lo; }
    else           { Ah = g_h_hi;  Al = g_h_lo;  Bh = g_wt2_hi; Bl = g_wt2_lo; }
    const __nv_bfloat16* Areg[3] = { Ah, Al, Ah };
    const __nv_bfloat16* Breg[3] = { Bh, Bh, Bl };

    size_t aBase = (size_t)e * CAP  * KDIM + (size_t)m0 * KDIM;
    size_t bBase = (size_t)e * NTOT * KDIM + (size_t)n0 * KDIM;

    int tid  = threadIdx.x;
    int lane = tid & 31;
    int wid  = tid >> 5;
    int wm   = (wid & 3) * 32;     // warp M offset (4 warps in M)
    int wn   = (wid >> 2) * 64;    // warp N offset (2 warps in N)

    // ---- loader mapping: thread -> rows (r0, r0+64), 16B col c0 ----
    int r0 = tid >> 2, c0 = tid & 3;
    int r1 = r0 + 64;
    uint32_t swz0 = (uint32_t)(r0 * 64 + ((c0 ^ ((r0 >> 1) & 3)) << 4));
    uint32_t swz1 = (uint32_t)(r1 * 64 + ((c0 ^ ((r1 >> 1) & 3)) << 4));
    size_t goff0 = (size_t)r0 * KDIM + c0 * 8;
    size_t goff1 = (size_t)r1 * KDIM + c0 * 8;

    // ---- per-lane ldmatrix offsets (ks=0); ks=1 XORs byte 32 -> k+16 ----
    int gq = lane >> 3;
    int ri = lane & 7;
    int a_r = ri + ((gq & 1) << 3);
    int a_c = (gq >> 1);
    uint32_t aoff[2];
#pragma unroll
    for (int mt = 0; mt < 2; mt++) {
        int m = wm + mt * 16 + a_r;
        aoff[mt] = (uint32_t)(m * 64 + ((a_c ^ ((m >> 1) & 3)) << 4));
    }
    int b_r = ri + ((gq >> 1) << 3);
    int b_c = (gq & 1);
    uint32_t boff[4];
#pragma unroll
    for (int bt = 0; bt < 4; bt++) {
        int n = wn + bt * 16 + b_r;
        boff[bt] = (uint32_t)(n * 64 + ((b_c ^ ((n >> 1) & 3)) << 4));
    }

    constexpr int KCH = KDIM / BK;
    constexpr int TCH = 3 * KCH;

    auto issue_load = [&](int t, int buf) {
        int reg = t / KCH;
        int k0  = (t - reg * KCH) * BK;
        const __nv_bfloat16* Ag = Areg[reg] + aBase + k0;
        const __nv_bfloat16* Bg = Breg[reg] + bBase + k0;
        uint32_t sA = smb + buf * STAGE_SZ;
        uint32_t sB = sA + STAGE_A;
        cp_async16(sA + swz0, Ag + goff0);
        cp_async16(sA + swz1, Ag + goff1);
        cp_async16(sB + swz0, Bg + goff0);
        cp_async16(sB + swz1, Bg + goff1);
    };

    float acc[2][8][4];
#pragma unroll
    for (int mt = 0; mt < 2; mt++)
#pragma unroll
        for (int nt = 0; nt < 8; nt++)
#pragma unroll
            for (int q = 0; q < 4; q++) acc[mt][nt][q] = 0.f;

    // ---- prologue: stages 0,1 in flight ----
    issue_load(0, 0); CP_COMMIT();
    issue_load(1, 1); CP_COMMIT();

    int buf = 0;
    for (int t = 0; t < TCH; t++) {
        CP_WAIT_1();                   // group for stage t complete
        __syncthreads();               // data visible + all done reading stage t-2's buffer

        int tn = t + 2;
        int nbuf = buf + 2; if (nbuf >= STAGES) nbuf -= STAGES;
        if (tn < TCH) { issue_load(tn, nbuf); CP_COMMIT(); }

        uint32_t sA = smb + buf * STAGE_SZ;
        uint32_t sB = sA + STAGE_A;
#pragma unroll
        for (int ks = 0; ks < 2; ks++) {
            uint32_t kx = ks << 5;
            uint32_t a[2][4];
            ldsm_x4(a[0][0], a[0][1], a[0][2], a[0][3], sA + (aoff[0] ^ kx));
            ldsm_x4(a[1][0], a[1][1], a[1][2], a[1][3], sA + (aoff[1] ^ kx));
            uint32_t b[4][4];
#pragma unroll
            for (int bt = 0; bt < 4; bt++)
                ldsm_x4(b[bt][0], b[bt][1], b[bt][2], b[bt][3], sB + (boff[bt] ^ kx));
#pragma unroll
            for (int mt = 0; mt < 2; mt++)
#pragma unroll
                for (int nt = 0; nt < 8; nt++)
                    mma16816(acc[mt][nt], a[mt], &b[nt >> 1][(nt & 1) * 2]);
        }
        if (++buf == STAGES) buf = 0;
    }

    // ---- epilogue ----
    int lrow = lane >> 2;
    int lcol = (lane & 3) * 2;
#pragma unroll
    for (int mt = 0; mt < 2; mt++) {
#pragma unroll
        for (int hh = 0; hh < 2; hh++) {
            int m = m0 + wm + mt * 16 + lrow + 8 * hh;
            size_t rb = ((size_t)e * CAP + m) * (size_t)NTOT;
#pragma unroll
            for (int nt = 0; nt < 8; nt++) {
                int cg = n0 + wn + nt * 8 + lcol;
                float2 bv = *(const float2*)(bias + (size_t)e * NTOT + cg);
                float v0 = acc[mt][nt][2 * hh]     + bv.x;
                float v1 = acc[mt][nt][2 * hh + 1] + bv.y;
                if (MODE == 0) {
                    v0 = gelu_f(v0);
                    v1 = gelu_f(v1);
                    unsigned short h0, l0, h1, l1;
                    split1(v0, h0, l0);
                    split1(v1, h1, l1);
                    *(uint32_t*)(g_h_hi + rb + cg) = (uint32_t)h0 | ((uint32_t)h1 << 16);
                    *(uint32_t*)(g_h_lo + rb + cg) = (uint32_t)l0 | ((uint32_t)l1 << 16);
                } else {
                    float2 o; o.x = v0; o.y = v1;
                    *(float2*)(g_ye + rb + cg) = o;
                }
            }
        }
    }
}

// ---------------- combine: gate-weighted sum over K=2 slots ----------------
__global__ void combine_kernel(float* __restrict__ out) {
    int t   = blockIdx.x;
    int tid = threadIdx.x;
    int   s0 = g_slot[2 * t];
    int   s1 = g_slot[2 * t + 1];
    float w0 = g_topv[2 * t];
    float w1 = g_topv[2 * t + 1];
    float4 r = make_float4(0.f, 0.f, 0.f, 0.f);
    if (s0 >= 0) {
        float4 y = *(const float4*)(g_ye + (size_t)s0 * DDIM + tid * 4);
        r.x += w0 * y.x; r.y += w0 * y.y; r.z += w0 * y.z; r.w += w0 * y.w;
    }
    if (s1 >= 0) {
        float4 y = *(const float4*)(g_ye + (size_t)s1 * DDIM + tid * 4);
        r.x += w1 * y.x; r.y += w1 * y.y; r.z += w1 * y.z; r.w += w1 * y.w;
    }
    *(float4*)(out + (size_t)t * DDIM + tid * 4) = r;
}

// ---------------- launch ----------------
extern "C" void kernel_launch(void* const* d_in, const int* in_sizes, int n_in,
                              void* d_out, int out_size) {
    const float* x  = (const float*)d_in[0];
    const float* gw = (const float*)d_in[1];
    const float* w1 = (const float*)d_in[2];
    const float* b1 = (const float*)d_in[3];
    const float* w2 = (const float*)d_in[4];
    const float* b2 = (const float*)d_in[5];
    float* out = (float*)d_out;

    // weight prep: w1 [E,D,F] -> g_wt1 [E,F,D]; w2 [E,F,D] -> g_wt2 [E,D,F]
    transpose_split<DDIM, FDIM, 1><<<dim3(FDIM / 32, DDIM / 32, NEXP), dim3(32, 8)>>>(w1);
    transpose_split<FDIM, DDIM, 2><<<dim3(DDIM / 32, FDIM / 32, NEXP), dim3(32, 8)>>>(w2);

    gating_kernel<<<T_TOK / 8, 256>>>(x, gw);
    hist_kernel<<<NB, CHUNK>>>();
    scan_kernel<<<1, 32>>>();
    rank_kernel<<<NB, CHUNK>>>();
    scatter_split<<<NFLAT, 128>>>(x);

    mma_gemm<DDIM, FDIM, 0><<<dim3(FDIM / BN, CAP / BM, NEXP), 256>>>(b1);
    mma_gemm<FDIM, DDIM, 1><<<dim3(DDIM / BN, CAP / BM, NEXP), 256>>>(b2);

    combine_kernel<<<T_TOK, 256>>>(out);
}

// round 15
// speedup vs baseline: 2.3711x; 1.0384x over previous
#include <cuda_runtime.h>
#include <cuda_bf16.h>
#include <math.h>
#include <stdint.h>

// ---------------- problem constants ----------------
#define T_TOK 16384
#define DDIM  1024
#define FDIM  4096
#define NEXP  16
#define KTOP  2
#define CAP   2560
#define NFLAT (T_TOK * KTOP)
#define NB    128
#define CHUNK 256

// ---------------- GEMM tiling ----------------
#define BM 128
#define BN 128
#define BK 32
#define STAGES 3
// Stage holds Ah | Al | Bh | Bl, each BM(=BN)xBK bf16 = 8192 B
#define OFF_AH 0
#define OFF_AL 8192
#define OFF_BH 16384
#define OFF_BL 24576
#define STAGE_SZ 32768
#define GEMM_SMEM (STAGES * STAGE_SZ)   // 98304 B dynamic

// ---------------- device scratch (static, zero-initialized) ----------------
__device__ __nv_bfloat16 g_xe_hi[NEXP * CAP * DDIM];
__device__ __nv_bfloat16 g_xe_lo[NEXP * CAP * DDIM];
__device__ __nv_bfloat16 g_h_hi [NEXP * CAP * FDIM];
__device__ __nv_bfloat16 g_h_lo [NEXP * CAP * FDIM];
__device__ float         g_ye   [NEXP * CAP * DDIM];
__device__ __nv_bfloat16 g_wt1_hi[NEXP * FDIM * DDIM];   // w1^T: [E][F][D] (K=D contiguous)
__device__ __nv_bfloat16 g_wt1_lo[NEXP * FDIM * DDIM];
__device__ __nv_bfloat16 g_wt2_hi[NEXP * DDIM * FDIM];   // w2^T: [E][D][F] (K=F contiguous)
__device__ __nv_bfloat16 g_wt2_lo[NEXP * DDIM * FDIM];
__device__ int   g_topi[NFLAT];
__device__ float g_topv[NFLAT];
__device__ int   g_slot[NFLAT];
__device__ int   g_bh  [NB * NEXP];
__device__ int   g_boff[NB * NEXP];
__device__ int   g_count[NEXP];

// ---------------- low-level helpers ----------------
__device__ __forceinline__ uint32_t smem_u32(const void* p) {
    uint32_t a;
    asm("{ .reg .u64 t; cvta.to.shared.u64 t, %1; cvt.u32.u64 %0, t; }" : "=r"(a) : "l"(p));
    return a;
}

__device__ __forceinline__ void cp_async16(uint32_t dst, const void* src) {
    asm volatile("cp.async.cg.shared.global [%0], [%1], 16;"
                 :: "r"(dst), "l"(__cvta_generic_to_global(src)) : "memory");
}
#define CP_COMMIT() asm volatile("cp.async.commit_group;" ::: "memory")
#define CP_WAIT_1() asm volatile("cp.async.wait_group 1;" ::: "memory")

__device__ __forceinline__ void ldsm_x4(uint32_t& r0, uint32_t& r1, uint32_t& r2, uint32_t& r3,
                                        uint32_t addr) {
    asm volatile("ldmatrix.sync.aligned.m8n8.x4.shared.b16 {%0,%1,%2,%3}, [%4];"
                 : "=r"(r0), "=r"(r1), "=r"(r2), "=r"(r3) : "r"(addr));
}

__device__ __forceinline__ void mma16816(float* d, const uint32_t* a, const uint32_t* b) {
    asm volatile("mma.sync.aligned.m16n8k16.row.col.f32.bf16.bf16.f32 "
                 "{%0,%1,%2,%3}, {%4,%5,%6,%7}, {%8,%9}, {%0,%1,%2,%3};"
                 : "+f"(d[0]), "+f"(d[1]), "+f"(d[2]), "+f"(d[3])
                 : "r"(a[0]), "r"(a[1]), "r"(a[2]), "r"(a[3]), "r"(b[0]), "r"(b[1]));
}

// hi/lo bf16 split
__device__ __forceinline__ void split1(float v, unsigned short& h, unsigned short& l) {
    __nv_bfloat16 hb = __float2bfloat16(v);
    float r = v - __bfloat162float(hb);
    __nv_bfloat16 lb = __float2bfloat16(r);
    h = __bfloat16_as_ushort(hb);
    l = __bfloat16_as_ushort(lb);
}

// ---------------- gating: warp per token ----------------
__global__ void gating_kernel(const float* __restrict__ x,
                              const float* __restrict__ gw) {
    int gtid = blockIdx.x * blockDim.x + threadIdx.x;
    int t    = gtid >> 5;
    int lane = gtid & 31;
    if (t >= T_TOK) return;

    const float* xr = x + (size_t)t * DDIM;
    float acc[NEXP];
#pragma unroll
    for (int e = 0; e < NEXP; e++) acc[e] = 0.f;
    for (int d = lane; d < DDIM; d += 32) {
        float xv = __ldg(xr + d);
        const float* g = gw + d * NEXP;
#pragma unroll
        for (int e = 0; e < NEXP; e++) acc[e] += xv * __ldg(g + e);
    }
#pragma unroll
    for (int off = 16; off > 0; off >>= 1)
#pragma unroll
        for (int e = 0; e < NEXP; e++)
            acc[e] += __shfl_xor_sync(0xffffffffu, acc[e], off);
    if (lane == 0) {
        int i0 = 0; float v0 = acc[0];
#pragma unroll
        for (int e = 1; e < NEXP; e++) if (acc[e] > v0) { v0 = acc[e]; i0 = e; }
        int i1 = -1; float v1 = -3.0e38f;
#pragma unroll
        for (int e = 0; e < NEXP; e++) if (e != i0 && acc[e] > v1) { v1 = acc[e]; i1 = e; }
        float w0 = 1.0f / (1.0f + expf(v1 - v0));
        g_topi[2 * t] = i0;  g_topi[2 * t + 1] = i1;
        g_topv[2 * t] = w0;  g_topv[2 * t + 1] = 1.0f - w0;
    }
}

// ---------------- dispatch chain (proven) ----------------
__global__ void hist_kernel() {
    __shared__ int h[NEXP];
    int tid = threadIdx.x;
    if (tid < NEXP) h[tid] = 0;
    __syncthreads();
    atomicAdd(&h[g_topi[blockIdx.x * CHUNK + tid]], 1);
    __syncthreads();
    if (tid < NEXP) g_bh[blockIdx.x * NEXP + tid] = h[tid];
}

__global__ void scan_kernel() {
    int e = threadIdx.x;
    if (e >= NEXP) return;
    int run = 0;
#pragma unroll 8
    for (int b = 0; b < NB; b++) { g_boff[b * NEXP + e] = run; run += g_bh[b * NEXP + e]; }
    g_count[e] = run;
}

__global__ void rank_kernel() {
    __shared__ int se[CHUNK];
    int tid = threadIdx.x;
    int i   = blockIdx.x * CHUNK + tid;
    int e   = g_topi[i];
    se[tid] = e;
    __syncthreads();
    int r = 0;
    for (int j = 0; j < tid; j++) r += (se[j] == e);
    int loc = g_boff[blockIdx.x * NEXP + e] + r;
    g_slot[i] = (loc < CAP) ? (e * CAP + loc) : -1;
}

// ---------------- scatter with bf16 hi/lo split ----------------
__global__ void scatter_split(const float* __restrict__ x) {
    int i = blockIdx.x;
    int s = g_slot[i];
    if (s < 0) return;
    int t = i >> 1;
    int tid = threadIdx.x;                        // 128 threads, 8 floats each
    const float* src = x + (size_t)t * DDIM + tid * 8;
    float v[8];
    *(float4*)(v)     = *(const float4*)(src);
    *(float4*)(v + 4) = *(const float4*)(src + 4);
    unsigned short h[8], l[8];
#pragma unroll
    for (int j = 0; j < 8; j++) split1(v[j], h[j], l[j]);
    ((uint4*)(g_xe_hi + (size_t)s * DDIM))[tid] = *(const uint4*)h;
    ((uint4*)(g_xe_lo + (size_t)s * DDIM))[tid] = *(const uint4*)l;
}

// ---------------- weight transpose + split ----------------
// Outputs referenced as __device__ globals from device code (R13 fix: host-side
// symbol args land in host memory via ATS).
// WHICH=1: w1 [E,D,F] -> g_wt1 [E,F,D];  WHICH=2: w2 [E,F,D] -> g_wt2 [E,D,F]
template <int R, int Cc, int WHICH>
__global__ void transpose_split(const float* __restrict__ in) {
    __nv_bfloat16* oh = (WHICH == 1) ? g_wt1_hi : g_wt2_hi;
    __nv_bfloat16* ol = (WHICH == 1) ? g_wt1_lo : g_wt2_lo;
    __shared__ float tile[32][33];
    int c0 = blockIdx.x * 32, r0 = blockIdx.y * 32, e = blockIdx.z;
    int tx = threadIdx.x, ty = threadIdx.y;
    const float* ip = in + (size_t)e * R * Cc;
#pragma unroll
    for (int i = 0; i < 4; i++)
        tile[ty + 8 * i][tx] = ip[(size_t)(r0 + ty + 8 * i) * Cc + c0 + tx];
    __syncthreads();
    size_t ob = (size_t)e * R * Cc;
#pragma unroll
    for (int i = 0; i < 4; i++) {
        float v = tile[tx][ty + 8 * i];
        unsigned short h, l;
        split1(v, h, l);
        size_t o = ob + (size_t)(c0 + ty + 8 * i) * R + r0 + tx;
        oh[o] = __ushort_as_bfloat16(h);
        ol[o] = __ushort_as_bfloat16(l);
    }
}

// ---------------- gelu (tanh approx, JAX default) ----------------
__device__ __forceinline__ float gelu_f(float v) {
    float u = 0.7978845608028654f * (v + 0.044715f * v * v * v);
    return 0.5f * v * (1.0f + tanhf(u));
}

// ---------------- tensor-core GEMM, fused bf16x3 split (single K pass) ------------------
// MODE 0: h  = gelu(xe @ w1 + b1) -> h hi/lo bf16   (KDIM=1024, NTOT=4096)
// MODE 1: ye =       h @ w2 + b2  -> ye fp32        (KDIM=4096, NTOT=1024)
// Per K-chunk, load Ah/Al/Bh/Bl once and issue Ah*Bh + Al*Bh + Ah*Bl.
// 3-stage cp.async pipeline, 96KB dynamic smem.
template <int KDIM, int NTOT, int MODE>
__global__ __launch_bounds__(256)
void mma_gemm(const float* __restrict__ bias) {
    int e   = blockIdx.z;
    int cnt = min(g_count[e], CAP);
    int m0  = blockIdx.y * BM;
    if (m0 >= cnt) return;
    int n0  = blockIdx.x * BN;

    extern __shared__ __align__(16) char sm[];
    uint32_t smb = smem_u32(sm);

    const __nv_bfloat16 *Ah, *Al, *Bh, *Bl;
    if (MODE == 0) { Ah = g_xe_hi; Al = g_xe_lo; Bh = g_wt1_hi; Bl = g_wt1_lo; }
    else           { Ah = g_h_hi;  Al = g_h_lo;  Bh = g_wt2_hi; Bl = g_wt2_lo; }

    size_t aBase = (size_t)e * CAP  * KDIM + (size_t)m0 * KDIM;
    size_t bBase = (size_t)e * NTOT * KDIM + (size_t)n0 * KDIM;

    int tid  = threadIdx.x;
    int lane = tid & 31;
    int wid  = tid >> 5;
    int wm   = (wid & 3) * 32;     // warp M offset (4 warps in M)
    int wn   = (wid >> 2) * 64;    // warp N offset (2 warps in N)

    // ---- loader mapping: thread -> rows (r0, r0+64), 16B col c0 ----
    int r0 = tid >> 2, c0 = tid & 3;
    int r1 = r0 + 64;
    uint32_t swz0 = (uint32_t)(r0 * 64 + ((c0 ^ ((r0 >> 1) & 3)) << 4));
    uint32_t swz1 = (uint32_t)(r1 * 64 + ((c0 ^ ((r1 >> 1) & 3)) << 4));
    size_t goff0 = (size_t)r0 * KDIM + c0 * 8;
    size_t goff1 = (size_t)r1 * KDIM + c0 * 8;

    // ---- per-lane ldmatrix offsets (ks=0); ks=1 XORs byte 32 -> k+16 ----
    int gq = lane >> 3;
    int ri = lane & 7;
    int a_r = ri + ((gq & 1) << 3);
    int a_c = (gq >> 1);
    uint32_t aoff[2];
#pragma unroll
    for (int mt = 0; mt < 2; mt++) {
        int m = wm + mt * 16 + a_r;
        aoff[mt] = (uint32_t)(m * 64 + ((a_c ^ ((m >> 1) & 3)) << 4));
    }
    int b_r = ri + ((gq >> 1) << 3);
    int b_c = (gq & 1);
    uint32_t boff[4];
#pragma unroll
    for (int bt = 0; bt < 4; bt++) {
        int n = wn + bt * 16 + b_r;
        boff[bt] = (uint32_t)(n * 64 + ((b_c ^ ((n >> 1) & 3)) << 4));
    }

    constexpr int KCH = KDIM / BK;

    auto issue_load = [&](int t, int buf) {
        int k0 = t * BK;
        uint32_t st = smb + buf * STAGE_SZ;
        const __nv_bfloat16* pAh = Ah + aBase + k0;
        const __nv_bfloat16* pAl = Al + aBase + k0;
        const __nv_bfloat16* pBh = Bh + bBase + k0;
        const __nv_bfloat16* pBl = Bl + bBase + k0;
        cp_async16(st + OFF_AH + swz0, pAh + goff0);
        cp_async16(st + OFF_AH + swz1, pAh + goff1);
        cp_async16(st + OFF_AL + swz0, pAl + goff0);
        cp_async16(st + OFF_AL + swz1, pAl + goff1);
        cp_async16(st + OFF_BH + swz0, pBh + goff0);
        cp_async16(st + OFF_BH + swz1, pBh + goff1);
        cp_async16(st + OFF_BL + swz0, pBl + goff0);
        cp_async16(st + OFF_BL + swz1, pBl + goff1);
    };

    float acc[2][8][4];
#pragma unroll
    for (int mt = 0; mt < 2; mt++)
#pragma unroll
        for (int nt = 0; nt < 8; nt++)
#pragma unroll
            for (int q = 0; q < 4; q++) acc[mt][nt][q] = 0.f;

    // ---- prologue: stages 0,1 in flight ----
    issue_load(0, 0); CP_COMMIT();
    issue_load(1, 1); CP_COMMIT();

    int buf = 0;
    for (int t = 0; t < KCH; t++) {
        CP_WAIT_1();                   // group for stage t complete
        __syncthreads();               // visible to all; prior readers done with this buffer

        int tn = t + 2;
        int nbuf = buf + 2; if (nbuf >= STAGES) nbuf -= STAGES;
        if (tn < KCH) { issue_load(tn, nbuf); CP_COMMIT(); }

        uint32_t st = smb + buf * STAGE_SZ;
#pragma unroll
        for (int ks = 0; ks < 2; ks++) {
            uint32_t kx = ks << 5;
            uint32_t ah[2][4], al[2][4];
            ldsm_x4(ah[0][0], ah[0][1], ah[0][2], ah[0][3], st + OFF_AH + (aoff[0] ^ kx));
            ldsm_x4(ah[1][0], ah[1][1], ah[1][2], ah[1][3], st + OFF_AH + (aoff[1] ^ kx));
            ldsm_x4(al[0][0], al[0][1], al[0][2], al[0][3], st + OFF_AL + (aoff[0] ^ kx));
            ldsm_x4(al[1][0], al[1][1], al[1][2], al[1][3], st + OFF_AL + (aoff[1] ^ kx));
            uint32_t b[4][4];
            // --- B hi: Ah*Bh and Al*Bh ---
#pragma unroll
            for (int bt = 0; bt < 4; bt++)
                ldsm_x4(b[bt][0], b[bt][1], b[bt][2], b[bt][3], st + OFF_BH + (boff[bt] ^ kx));
#pragma unroll
            for (int mt = 0; mt < 2; mt++)
#pragma unroll
                for (int nt = 0; nt < 8; nt++) {
                    mma16816(acc[mt][nt], ah[mt], &b[nt >> 1][(nt & 1) * 2]);
                    mma16816(acc[mt][nt], al[mt], &b[nt >> 1][(nt & 1) * 2]);
                }
            // --- B lo: Ah*Bl (reuse b registers) ---
#pragma unroll
            for (int bt = 0; bt < 4; bt++)
                ldsm_x4(b[bt][0], b[bt][1], b[bt][2], b[bt][3], st + OFF_BL + (boff[bt] ^ kx));
#pragma unroll
            for (int mt = 0; mt < 2; mt++)
#pragma unroll
                for (int nt = 0; nt < 8; nt++)
                    mma16816(acc[mt][nt], ah[mt], &b[nt >> 1][(nt & 1) * 2]);
        }
        if (++buf == STAGES) buf = 0;
    }

    // ---- epilogue ----
    int lrow = lane >> 2;
    int lcol = (lane & 3) * 2;
#pragma unroll
    for (int mt = 0; mt < 2; mt++) {
#pragma unroll
        for (int hh = 0; hh < 2; hh++) {
            int m = m0 + wm + mt * 16 + lrow + 8 * hh;
            size_t rb = ((size_t)e * CAP + m) * (size_t)NTOT;
#pragma unroll
            for (int nt = 0; nt < 8; nt++) {
                int cg = n0 + wn + nt * 8 + lcol;
                float2 bv = *(const float2*)(bias + (size_t)e * NTOT + cg);
                float v0 = acc[mt][nt][2 * hh]     + bv.x;
                float v1 = acc[mt][nt][2 * hh + 1] + bv.y;
                if (MODE == 0) {
                    v0 = gelu_f(v0);
                    v1 = gelu_f(v1);
                    unsigned short h0, l0, h1, l1;
                    split1(v0, h0, l0);
                    split1(v1, h1, l1);
                    *(uint32_t*)(g_h_hi + rb + cg) = (uint32_t)h0 | ((uint32_t)h1 << 16);
                    *(uint32_t*)(g_h_lo + rb + cg) = (uint32_t)l0 | ((uint32_t)l1 << 16);
                } else {
                    float2 o; o.x = v0; o.y = v1;
                    *(float2*)(g_ye + rb + cg) = o;
                }
            }
        }
    }
}

// ---------------- combine: gate-weighted sum over K=2 slots ----------------
__global__ void combine_kernel(float* __restrict__ out) {
    int t   = blockIdx.x;
    int tid = threadIdx.x;
    int   s0 = g_slot[2 * t];
    int   s1 = g_slot[2 * t + 1];
    float w0 = g_topv[2 * t];
    float w1 = g_topv[2 * t + 1];
    float4 r = make_float4(0.f, 0.f, 0.f, 0.f);
    if (s0 >= 0) {
        float4 y = *(const float4*)(g_ye + (size_t)s0 * DDIM + tid * 4);
        r.x += w0 * y.x; r.y += w0 * y.y; r.z += w0 * y.z; r.w += w0 * y.w;
    }
    if (s1 >= 0) {
        float4 y = *(const float4*)(g_ye + (size_t)s1 * DDIM + tid * 4);
        r.x += w1 * y.x; r.y += w1 * y.y; r.z += w1 * y.z; r.w += w1 * y.w;
    }
    *(float4*)(out + (size_t)t * DDIM + tid * 4) = r;
}

// ---------------- launch ----------------
extern "C" void kernel_launch(void* const* d_in, const int* in_sizes, int n_in,
                              void* d_out, int out_size) {
    const float* x  = (const float*)d_in[0];
    const float* gw = (const float*)d_in[1];
    const float* w1 = (const float*)d_in[2];
    const float* b1 = (const float*)d_in[3];
    const float* w2 = (const float*)d_in[4];
    const float* b2 = (const float*)d_in[5];
    float* out = (float*)d_out;

    cudaFuncSetAttribute(mma_gemm<DDIM, FDIM, 0>,
                         cudaFuncAttributeMaxDynamicSharedMemorySize, GEMM_SMEM);
    cudaFuncSetAttribute(mma_gemm<FDIM, DDIM, 1>,
                         cudaFuncAttributeMaxDynamicSharedMemorySize, GEMM_SMEM);

    // weight prep: w1 [E,D,F] -> g_wt1 [E,F,D]; w2 [E,F,D] -> g_wt2 [E,D,F]
    transpose_split<DDIM, FDIM, 1><<<dim3(FDIM / 32, DDIM / 32, NEXP), dim3(32, 8)>>>(w1);
    transpose_split<FDIM, DDIM, 2><<<dim3(DDIM / 32, FDIM / 32, NEXP), dim3(32, 8)>>>(w2);

    gating_kernel<<<T_TOK / 8, 256>>>(x, gw);
    hist_kernel<<<NB, CHUNK>>>();
    scan_kernel<<<1, 32>>>();
    rank_kernel<<<NB, CHUNK>>>();
    scatter_split<<<NFLAT, 128>>>(x);

    mma_gemm<DDIM, FDIM, 0><<<dim3(FDIM / BN, CAP / BM, NEXP), 256, GEMM_SMEM>>>(b1);
    mma_gemm<FDIM, DDIM, 1><<<dim3(DDIM / BN, CAP / BM, NEXP), 256, GEMM_SMEM>>>(b2);

    combine_kernel<<<T_TOK, 256>>>(out);
}

// round 16
// speedup vs baseline: 2.7410x; 1.1560x over previous
#include <cuda_runtime.h>
#include <cuda_bf16.h>
#include <math.h>
#include <stdint.h>

// ---------------- problem constants ----------------
#define T_TOK 16384
#define DDIM  1024
#define FDIM  4096
#define NEXP  16
#define KTOP  2
#define CAP   2560
#define NFLAT (T_TOK * KTOP)
#define NB    128
#define CHUNK 256

// ---------------- GEMM tiling ----------------
#define BM 128
#define BN 128
#define BK 32
#define STAGES 3
// Stage holds Ah | Al | Bh | Bl, each BM(=BN)xBK bf16 = 8192 B
#define OFF_AH 0
#define OFF_AL 8192
#define OFF_BH 16384
#define OFF_BL 24576
#define STAGE_SZ 32768
#define GEMM_SMEM (STAGES * STAGE_SZ)   // 98304 B dynamic; 2 CTAs = 192KB <= 227KB

// ---------------- device scratch (static, zero-initialized) ----------------
__device__ __nv_bfloat16 g_xe_hi[NEXP * CAP * DDIM];
__device__ __nv_bfloat16 g_xe_lo[NEXP * CAP * DDIM];
__device__ __nv_bfloat16 g_h_hi [NEXP * CAP * FDIM];
__device__ __nv_bfloat16 g_h_lo [NEXP * CAP * FDIM];
__device__ float         g_ye   [NEXP * CAP * DDIM];
__device__ __nv_bfloat16 g_wt1_hi[NEXP * FDIM * DDIM];   // w1^T: [E][F][D] (K=D contiguous)
__device__ __nv_bfloat16 g_wt1_lo[NEXP * FDIM * DDIM];
__device__ __nv_bfloat16 g_wt2_hi[NEXP * DDIM * FDIM];   // w2^T: [E][D][F] (K=F contiguous)
__device__ __nv_bfloat16 g_wt2_lo[NEXP * DDIM * FDIM];
__device__ int   g_topi[NFLAT];
__device__ float g_topv[NFLAT];
__device__ int   g_slot[NFLAT];
__device__ int   g_bh  [NB * NEXP];
__device__ int   g_boff[NB * NEXP];
__device__ int   g_count[NEXP];

// ---------------- low-level helpers ----------------
__device__ __forceinline__ uint32_t smem_u32(const void* p) {
    uint32_t a;
    asm("{ .reg .u64 t; cvta.to.shared.u64 t, %1; cvt.u32.u64 %0, t; }" : "=r"(a) : "l"(p));
    return a;
}

__device__ __forceinline__ void cp_async16(uint32_t dst, const void* src) {
    asm volatile("cp.async.cg.shared.global [%0], [%1], 16;"
                 :: "r"(dst), "l"(__cvta_generic_to_global(src)) : "memory");
}
#define CP_COMMIT() asm volatile("cp.async.commit_group;" ::: "memory")
#define CP_WAIT_1() asm volatile("cp.async.wait_group 1;" ::: "memory")

__device__ __forceinline__ void ldsm_x4(uint32_t& r0, uint32_t& r1, uint32_t& r2, uint32_t& r3,
                                        uint32_t addr) {
    asm volatile("ldmatrix.sync.aligned.m8n8.x4.shared.b16 {%0,%1,%2,%3}, [%4];"
                 : "=r"(r0), "=r"(r1), "=r"(r2), "=r"(r3) : "r"(addr));
}

__device__ __forceinline__ void mma16816(float* d, const uint32_t* a, const uint32_t* b) {
    asm volatile("mma.sync.aligned.m16n8k16.row.col.f32.bf16.bf16.f32 "
                 "{%0,%1,%2,%3}, {%4,%5,%6,%7}, {%8,%9}, {%0,%1,%2,%3};"
                 : "+f"(d[0]), "+f"(d[1]), "+f"(d[2]), "+f"(d[3])
                 : "r"(a[0]), "r"(a[1]), "r"(a[2]), "r"(a[3]), "r"(b[0]), "r"(b[1]));
}

// hi/lo bf16 split
__device__ __forceinline__ void split1(float v, unsigned short& h, unsigned short& l) {
    __nv_bfloat16 hb = __float2bfloat16(v);
    float r = v - __bfloat162float(hb);
    __nv_bfloat16 lb = __float2bfloat16(r);
    h = __bfloat16_as_ushort(hb);
    l = __bfloat16_as_ushort(lb);
}

// ---------------- gating: warp per token ----------------
__global__ void gating_kernel(const float* __restrict__ x,
                              const float* __restrict__ gw) {
    int gtid = blockIdx.x * blockDim.x + threadIdx.x;
    int t    = gtid >> 5;
    int lane = gtid & 31;
    if (t >= T_TOK) return;

    const float* xr = x + (size_t)t * DDIM;
    float acc[NEXP];
#pragma unroll
    for (int e = 0; e < NEXP; e++) acc[e] = 0.f;
    for (int d = lane; d < DDIM; d += 32) {
        float xv = __ldg(xr + d);
        const float* g = gw + d * NEXP;
#pragma unroll
        for (int e = 0; e < NEXP; e++) acc[e] += xv * __ldg(g + e);
    }
#pragma unroll
    for (int off = 16; off > 0; off >>= 1)
#pragma unroll
        for (int e = 0; e < NEXP; e++)
            acc[e] += __shfl_xor_sync(0xffffffffu, acc[e], off);
    if (lane == 0) {
        int i0 = 0; float v0 = acc[0];
#pragma unroll
        for (int e = 1; e < NEXP; e++) if (acc[e] > v0) { v0 = acc[e]; i0 = e; }
        int i1 = -1; float v1 = -3.0e38f;
#pragma unroll
        for (int e = 0; e < NEXP; e++) if (e != i0 && acc[e] > v1) { v1 = acc[e]; i1 = e; }
        float w0 = 1.0f / (1.0f + expf(v1 - v0));
        g_topi[2 * t] = i0;  g_topi[2 * t + 1] = i1;
        g_topv[2 * t] = w0;  g_topv[2 * t + 1] = 1.0f - w0;
    }
}

// ---------------- dispatch chain (proven) ----------------
__global__ void hist_kernel() {
    __shared__ int h[NEXP];
    int tid = threadIdx.x;
    if (tid < NEXP) h[tid] = 0;
    __syncthreads();
    atomicAdd(&h[g_topi[blockIdx.x * CHUNK + tid]], 1);
    __syncthreads();
    if (tid < NEXP) g_bh[blockIdx.x * NEXP + tid] = h[tid];
}

__global__ void scan_kernel() {
    int e = threadIdx.x;
    if (e >= NEXP) return;
    int run = 0;
#pragma unroll 8
    for (int b = 0; b < NB; b++) { g_boff[b * NEXP + e] = run; run += g_bh[b * NEXP + e]; }
    g_count[e] = run;
}

__global__ void rank_kernel() {
    __shared__ int se[CHUNK];
    int tid = threadIdx.x;
    int i   = blockIdx.x * CHUNK + tid;
    int e   = g_topi[i];
    se[tid] = e;
    __syncthreads();
    int r = 0;
    for (int j = 0; j < tid; j++) r += (se[j] == e);
    int loc = g_boff[blockIdx.x * NEXP + e] + r;
    g_slot[i] = (loc < CAP) ? (e * CAP + loc) : -1;
}

// ---------------- scatter with bf16 hi/lo split ----------------
__global__ void scatter_split(const float* __restrict__ x) {
    int i = blockIdx.x;
    int s = g_slot[i];
    if (s < 0) return;
    int t = i >> 1;
    int tid = threadIdx.x;                        // 128 threads, 8 floats each
    const float* src = x + (size_t)t * DDIM + tid * 8;
    float v[8];
    *(float4*)(v)     = *(const float4*)(src);
    *(float4*)(v + 4) = *(const float4*)(src + 4);
    unsigned short h[8], l[8];
#pragma unroll
    for (int j = 0; j < 8; j++) split1(v[j], h[j], l[j]);
    ((uint4*)(g_xe_hi + (size_t)s * DDIM))[tid] = *(const uint4*)h;
    ((uint4*)(g_xe_lo + (size_t)s * DDIM))[tid] = *(const uint4*)l;
}

// ---------------- weight transpose + split ----------------
// Outputs referenced as __device__ globals from device code (R13 fix: host-side
// symbol args land in host memory via ATS).
// WHICH=1: w1 [E,D,F] -> g_wt1 [E,F,D];  WHICH=2: w2 [E,F,D] -> g_wt2 [E,D,F]
template <int R, int Cc, int WHICH>
__global__ void transpose_split(const float* __restrict__ in) {
    __nv_bfloat16* oh = (WHICH == 1) ? g_wt1_hi : g_wt2_hi;
    __nv_bfloat16* ol = (WHICH == 1) ? g_wt1_lo : g_wt2_lo;
    __shared__ float tile[32][33];
    int c0 = blockIdx.x * 32, r0 = blockIdx.y * 32, e = blockIdx.z;
    int tx = threadIdx.x, ty = threadIdx.y;
    const float* ip = in + (size_t)e * R * Cc;
#pragma unroll
    for (int i = 0; i < 4; i++)
        tile[ty + 8 * i][tx] = ip[(size_t)(r0 + ty + 8 * i) * Cc + c0 + tx];
    __syncthreads();
    size_t ob = (size_t)e * R * Cc;
#pragma unroll
    for (int i = 0; i < 4; i++) {
        float v = tile[tx][ty + 8 * i];
        unsigned short h, l;
        split1(v, h, l);
        size_t o = ob + (size_t)(c0 + ty + 8 * i) * R + r0 + tx;
        oh[o] = __ushort_as_bfloat16(h);
        ol[o] = __ushort_as_bfloat16(l);
    }
}

// ---------------- gelu (tanh approx, JAX default) ----------------
__device__ __forceinline__ float gelu_f(float v) {
    float u = 0.7978845608028654f * (v + 0.044715f * v * v * v);
    return 0.5f * v * (1.0f + tanhf(u));
}

// ---------------- tensor-core GEMM, fused bf16x3 split (single K pass) ------------------
// MODE 0: h  = gelu(xe @ w1 + b1) -> h hi/lo bf16   (KDIM=1024, NTOT=4096)
// MODE 1: ye =       h @ w2 + b2  -> ye fp32        (KDIM=4096, NTOT=1024)
// Per K-chunk, load Ah/Al/Bh/Bl once and issue Ah*Bh + Al*Bh + Ah*Bl.
// R16: __launch_bounds__(256, 2) caps regs at 128 -> 2 CTAs/SM (4 warps/SMSP)
// so one CTA's load waits are hidden behind the other's MMA issue.
template <int KDIM, int NTOT, int MODE>
__global__ __launch_bounds__(256, 2)
void mma_gemm(const float* __restrict__ bias) {
    int e   = blockIdx.z;
    int cnt = min(g_count[e], CAP);
    int m0  = blockIdx.y * BM;
    if (m0 >= cnt) return;
    int n0  = blockIdx.x * BN;

    extern __shared__ __align__(16) char sm[];
    uint32_t smb = smem_u32(sm);

    const __nv_bfloat16 *Ah, *Al, *Bh, *Bl;
    if (MODE == 0) { Ah = g_xe_hi; Al = g_xe_lo; Bh = g_wt1_hi; Bl = g_wt1_lo; }
    else           { Ah = g_h_hi;  Al = g_h_lo;  Bh = g_wt2_hi; Bl = g_wt2_lo; }

    size_t aBase = (size_t)e * CAP  * KDIM + (size_t)m0 * KDIM;
    size_t bBase = (size_t)e * NTOT * KDIM + (size_t)n0 * KDIM;

    int tid  = threadIdx.x;
    int lane = tid & 31;
    int wid  = tid >> 5;
    int wm   = (wid & 3) * 32;     // warp M offset (4 warps in M)
    int wn   = (wid >> 2) * 64;    // warp N offset (2 warps in N)

    // ---- loader mapping: thread -> rows (r0, r0+64), 16B col c0 ----
    int r0 = tid >> 2, c0 = tid & 3;
    int r1 = r0 + 64;
    uint32_t swz0 = (uint32_t)(r0 * 64 + ((c0 ^ ((r0 >> 1) & 3)) << 4));
    uint32_t swz1 = (uint32_t)(r1 * 64 + ((c0 ^ ((r1 >> 1) & 3)) << 4));
    size_t goff0 = (size_t)r0 * KDIM + c0 * 8;
    size_t goff1 = (size_t)r1 * KDIM + c0 * 8;

    // ---- per-lane ldmatrix offsets (ks=0); ks=1 XORs byte 32 -> k+16 ----
    int gq = lane >> 3;
    int ri = lane & 7;
    int a_r = ri + ((gq & 1) << 3);
    int a_c = (gq >> 1);
    uint32_t aoff[2];
#pragma unroll
    for (int mt = 0; mt < 2; mt++) {
        int m = wm + mt * 16 + a_r;
        aoff[mt] = (uint32_t)(m * 64 + ((a_c ^ ((m >> 1) & 3)) << 4));
    }
    int b_r = ri + ((gq >> 1) << 3);
    int b_c = (gq & 1);
    uint32_t boff[4];
#pragma unroll
    for (int bt = 0; bt < 4; bt++) {
        int n = wn + bt * 16 + b_r;
        boff[bt] = (uint32_t)(n * 64 + ((b_c ^ ((n >> 1) & 3)) << 4));
    }

    constexpr int KCH = KDIM / BK;

    auto issue_load = [&](int t, int buf) {
        int k0 = t * BK;
        uint32_t st = smb + buf * STAGE_SZ;
        const __nv_bfloat16* pAh = Ah + aBase + k0;
        const __nv_bfloat16* pAl = Al + aBase + k0;
        const __nv_bfloat16* pBh = Bh + bBase + k0;
        const __nv_bfloat16* pBl = Bl + bBase + k0;
        cp_async16(st + OFF_AH + swz0, pAh + goff0);
        cp_async16(st + OFF_AH + swz1, pAh + goff1);
        cp_async16(st + OFF_AL + swz0, pAl + goff0);
        cp_async16(st + OFF_AL + swz1, pAl + goff1);
        cp_async16(st + OFF_BH + swz0, pBh + goff0);
        cp_async16(st + OFF_BH + swz1, pBh + goff1);
        cp_async16(st + OFF_BL + swz0, pBl + goff0);
        cp_async16(st + OFF_BL + swz1, pBl + goff1);
    };

    float acc[2][8][4];
#pragma unroll
    for (int mt = 0; mt < 2; mt++)
#pragma unroll
        for (int nt = 0; nt < 8; nt++)
#pragma unroll
            for (int q = 0; q < 4; q++) acc[mt][nt][q] = 0.f;

    // ---- prologue: stages 0,1 in flight ----
    issue_load(0, 0); CP_COMMIT();
    issue_load(1, 1); CP_COMMIT();

    int buf = 0;
    for (int t = 0; t < KCH; t++) {
        CP_WAIT_1();                   // group for stage t complete
        __syncthreads();               // visible to all; prior readers done with this buffer

        int tn = t + 2;
        int nbuf = buf + 2; if (nbuf >= STAGES) nbuf -= STAGES;
        if (tn < KCH) { issue_load(tn, nbuf); CP_COMMIT(); }

        uint32_t st = smb + buf * STAGE_SZ;
#pragma unroll
        for (int ks = 0; ks < 2; ks++) {
            uint32_t kx = ks << 5;
            uint32_t ah[2][4], al[2][4];
            ldsm_x4(ah[0][0], ah[0][1], ah[0][2], ah[0][3], st + OFF_AH + (aoff[0] ^ kx));
            ldsm_x4(ah[1][0], ah[1][1], ah[1][2], ah[1][3], st + OFF_AH + (aoff[1] ^ kx));
            ldsm_x4(al[0][0], al[0][1], al[0][2], al[0][3], st + OFF_AL + (aoff[0] ^ kx));
            ldsm_x4(al[1][0], al[1][1], al[1][2], al[1][3], st + OFF_AL + (aoff[1] ^ kx));
            uint32_t b[4][4];
            // --- B hi: Ah*Bh and Al*Bh ---
#pragma unroll
            for (int bt = 0; bt < 4; bt++)
                ldsm_x4(b[bt][0], b[bt][1], b[bt][2], b[bt][3], st + OFF_BH + (boff[bt] ^ kx));
#pragma unroll
            for (int mt = 0; mt < 2; mt++)
#pragma unroll
                for (int nt = 0; nt < 8; nt++) {
                    mma16816(acc[mt][nt], ah[mt], &b[nt >> 1][(nt & 1) * 2]);
                    mma16816(acc[mt][nt], al[mt], &b[nt >> 1][(nt & 1) * 2]);
                }
            // --- B lo: Ah*Bl (reuse b registers) ---
#pragma unroll
            for (int bt = 0; bt < 4; bt++)
                ldsm_x4(b[bt][0], b[bt][1], b[bt][2], b[bt][3], st + OFF_BL + (boff[bt] ^ kx));
#pragma unroll
            for (int mt = 0; mt < 2; mt++)
#pragma unroll
                for (int nt = 0; nt < 8; nt++)
                    mma16816(acc[mt][nt], ah[mt], &b[nt >> 1][(nt & 1) * 2]);
        }
        if (++buf == STAGES) buf = 0;
    }

    // ---- epilogue ----
    int lrow = lane >> 2;
    int lcol = (lane & 3) * 2;
#pragma unroll
    for (int mt = 0; mt < 2; mt++) {
#pragma unroll
        for (int hh = 0; hh < 2; hh++) {
            int m = m0 + wm + mt * 16 + lrow + 8 * hh;
            size_t rb = ((size_t)e * CAP + m) * (size_t)NTOT;
#pragma unroll
            for (int nt = 0; nt < 8; nt++) {
                int cg = n0 + wn + nt * 8 + lcol;
                float2 bv = *(const float2*)(bias + (size_t)e * NTOT + cg);
                float v0 = acc[mt][nt][2 * hh]     + bv.x;
                float v1 = acc[mt][nt][2 * hh + 1] + bv.y;
                if (MODE == 0) {
                    v0 = gelu_f(v0);
                    v1 = gelu_f(v1);
                    unsigned short h0, l0, h1, l1;
                    split1(v0, h0, l0);
                    split1(v1, h1, l1);
                    *(uint32_t*)(g_h_hi + rb + cg) = (uint32_t)h0 | ((uint32_t)h1 << 16);
                    *(uint32_t*)(g_h_lo + rb + cg) = (uint32_t)l0 | ((uint32_t)l1 << 16);
                } else {
                    float2 o; o.x = v0; o.y = v1;
                    *(float2*)(g_ye + rb + cg) = o;
                }
            }
        }
    }
}

// ---------------- combine: gate-weighted sum over K=2 slots ----------------
__global__ void combine_kernel(float* __restrict__ out) {
    int t   = blockIdx.x;
    int tid = threadIdx.x;
    int   s0 = g_slot[2 * t];
    int   s1 = g_slot[2 * t + 1];
    float w0 = g_topv[2 * t];
    float w1 = g_topv[2 * t + 1];
    float4 r = make_float4(0.f, 0.f, 0.f, 0.f);
    if (s0 >= 0) {
        float4 y = *(const float4*)(g_ye + (size_t)s0 * DDIM + tid * 4);
        r.x += w0 * y.x; r.y += w0 * y.y; r.z += w0 * y.z; r.w += w0 * y.w;
    }
    if (s1 >= 0) {
        float4 y = *(const float4*)(g_ye + (size_t)s1 * DDIM + tid * 4);
        r.x += w1 * y.x; r.y += w1 * y.y; r.z += w1 * y.z; r.w += w1 * y.w;
    }
    *(float4*)(out + (size_t)t * DDIM + tid * 4) = r;
}

// ---------------- launch ----------------
extern "C" void kernel_launch(void* const* d_in, const int* in_sizes, int n_in,
                              void* d_out, int out_size) {
    const float* x  = (const float*)d_in[0];
    const float* gw = (const float*)d_in[1];
    const float* w1 = (const float*)d_in[2];
    const float* b1 = (const float*)d_in[3];
    const float* w2 = (const float*)d_in[4];
    const float* b2 = (const float*)d_in[5];
    float* out = (float*)d_out;

    cudaFuncSetAttribute(mma_gemm<DDIM, FDIM, 0>,
                         cudaFuncAttributeMaxDynamicSharedMemorySize, GEMM_SMEM);
    cudaFuncSetAttribute(mma_gemm<FDIM, DDIM, 1>,
                         cudaFuncAttributeMaxDynamicSharedMemorySize, GEMM_SMEM);

    // weight prep: w1 [E,D,F] -> g_wt1 [E,F,D]; w2 [E,F,D] -> g_wt2 [E,D,F]
    transpose_split<DDIM, FDIM, 1><<<dim3(FDIM / 32, DDIM / 32, NEXP), dim3(32, 8)>>>(w1);
    transpose_split<FDIM, DDIM, 2><<<dim3(DDIM / 32, FDIM / 32, NEXP), dim3(32, 8)>>>(w2);

    gating_kernel<<<T_TOK / 8, 256>>>(x, gw);
    hist_kernel<<<NB, CHUNK>>>();
    scan_kernel<<<1, 32>>>();
    rank_kernel<<<NB, CHUNK>>>();
    scatter_split<<<NFLAT, 128>>>(x);

    mma_gemm<DDIM, FDIM, 0><<<dim3(FDIM / BN, CAP / BM, NEXP), 256, GEMM_SMEM>>>(b1);
    mma_gemm<FDIM, DDIM, 1><<<dim3(DDIM / BN, CAP / BM, NEXP), 256, GEMM_SMEM>>>(b2);

    combine_kernel<<<T_TOK, 256>>>(out);
}

// round 17
// speedup vs baseline: 3.9112x; 1.4270x over previous
#include <cuda_runtime.h>
#include <cuda_fp16.h>
#include <math.h>
#include <stdint.h>

// ---------------- problem constants ----------------
#define T_TOK 16384
#define DDIM  1024
#define FDIM  4096
#define NEXP  16
#define KTOP  2
#define CAP   2560
#define NFLAT (T_TOK * KTOP)
#define NB    128
#define CHUNK 256

// ---------------- GEMM tiling ----------------
#define BM 128
#define BN 128
#define BK 32
#define STAGES 3
// Stage holds Ah | Al | B, each BM(=BN)xBK fp16 = 8192 B
#define OFF_AH 0
#define OFF_AL 8192
#define OFF_B  16384
#define STAGE_SZ 24576
#define GEMM_SMEM (STAGES * STAGE_SZ)   // 73728 B dynamic; 2 CTAs = 144KB <= 227KB

// ---------------- device scratch (static, zero-initialized) ----------------
__device__ __half g_xe_hi[NEXP * CAP * DDIM];
__device__ __half g_xe_lo[NEXP * CAP * DDIM];
__device__ __half g_h_hi [NEXP * CAP * FDIM];
__device__ __half g_h_lo [NEXP * CAP * FDIM];
__device__ float  g_ye   [NEXP * CAP * DDIM];
__device__ __half g_wt1[NEXP * FDIM * DDIM];   // w1^T: [E][F][D] (K=D contiguous), fp16
__device__ __half g_wt2[NEXP * DDIM * FDIM];   // w2^T: [E][D][F] (K=F contiguous), fp16
__device__ int   g_topi[NFLAT];
__device__ float g_topv[NFLAT];
__device__ int   g_slot[NFLAT];
__device__ int   g_bh  [NB * NEXP];
__device__ int   g_boff[NB * NEXP];
__device__ int   g_count[NEXP];

// ---------------- low-level helpers ----------------
__device__ __forceinline__ uint32_t smem_u32(const void* p) {
    uint32_t a;
    asm("{ .reg .u64 t; cvta.to.shared.u64 t, %1; cvt.u32.u64 %0, t; }" : "=r"(a) : "l"(p));
    return a;
}

__device__ __forceinline__ void cp_async16(uint32_t dst, const void* src) {
    asm volatile("cp.async.cg.shared.global [%0], [%1], 16;"
                 :: "r"(dst), "l"(__cvta_generic_to_global(src)) : "memory");
}
#define CP_COMMIT() asm volatile("cp.async.commit_group;" ::: "memory")
#define CP_WAIT_1() asm volatile("cp.async.wait_group 1;" ::: "memory")

__device__ __forceinline__ void ldsm_x4(uint32_t& r0, uint32_t& r1, uint32_t& r2, uint32_t& r3,
                                        uint32_t addr) {
    asm volatile("ldmatrix.sync.aligned.m8n8.x4.shared.b16 {%0,%1,%2,%3}, [%4];"
                 : "=r"(r0), "=r"(r1), "=r"(r2), "=r"(r3) : "r"(addr));
}

__device__ __forceinline__ void mma16816(float* d, const uint32_t* a, const uint32_t* b) {
    asm volatile("mma.sync.aligned.m16n8k16.row.col.f32.f16.f16.f32 "
                 "{%0,%1,%2,%3}, {%4,%5,%6,%7}, {%8,%9}, {%0,%1,%2,%3};"
                 : "+f"(d[0]), "+f"(d[1]), "+f"(d[2]), "+f"(d[3])
                 : "r"(a[0]), "r"(a[1]), "r"(a[2]), "r"(a[3]), "r"(b[0]), "r"(b[1]));
}

// fp16 hi/lo exact split: v = hi + lo with residual ~2^-22*v
__device__ __forceinline__ void split1(float v, unsigned short& h, unsigned short& l) {
    __half hb = __float2half_rn(v);
    float r = v - __half2float(hb);
    __half lb = __float2half_rn(r);
    h = __half_as_ushort(hb);
    l = __half_as_ushort(lb);
}

// ---------------- gating: warp per token ----------------
__global__ void gating_kernel(const float* __restrict__ x,
                              const float* __restrict__ gw) {
    int gtid = blockIdx.x * blockDim.x + threadIdx.x;
    int t    = gtid >> 5;
    int lane = gtid & 31;
    if (t >= T_TOK) return;

    const float* xr = x + (size_t)t * DDIM;
    float acc[NEXP];
#pragma unroll
    for (int e = 0; e < NEXP; e++) acc[e] = 0.f;
    for (int d = lane; d < DDIM; d += 32) {
        float xv = __ldg(xr + d);
        const float* g = gw + d * NEXP;
#pragma unroll
        for (int e = 0; e < NEXP; e++) acc[e] += xv * __ldg(g + e);
    }
#pragma unroll
    for (int off = 16; off > 0; off >>= 1)
#pragma unroll
        for (int e = 0; e < NEXP; e++)
            acc[e] += __shfl_xor_sync(0xffffffffu, acc[e], off);
    if (lane == 0) {
        int i0 = 0; float v0 = acc[0];
#pragma unroll
        for (int e = 1; e < NEXP; e++) if (acc[e] > v0) { v0 = acc[e]; i0 = e; }
        int i1 = -1; float v1 = -3.0e38f;
#pragma unroll
        for (int e = 0; e < NEXP; e++) if (e != i0 && acc[e] > v1) { v1 = acc[e]; i1 = e; }
        float w0 = 1.0f / (1.0f + expf(v1 - v0));
        g_topi[2 * t] = i0;  g_topi[2 * t + 1] = i1;
        g_topv[2 * t] = w0;  g_topv[2 * t + 1] = 1.0f - w0;
    }
}

// ---------------- dispatch chain (proven) ----------------
__global__ void hist_kernel() {
    __shared__ int h[NEXP];
    int tid = threadIdx.x;
    if (tid < NEXP) h[tid] = 0;
    __syncthreads();
    atomicAdd(&h[g_topi[blockIdx.x * CHUNK + tid]], 1);
    __syncthreads();
    if (tid < NEXP) g_bh[blockIdx.x * NEXP + tid] = h[tid];
}

__global__ void scan_kernel() {
    int e = threadIdx.x;
    if (e >= NEXP) return;
    int run = 0;
#pragma unroll 8
    for (int b = 0; b < NB; b++) { g_boff[b * NEXP + e] = run; run += g_bh[b * NEXP + e]; }
    g_count[e] = run;
}

__global__ void rank_kernel() {
    __shared__ int se[CHUNK];
    int tid = threadIdx.x;
    int i   = blockIdx.x * CHUNK + tid;
    int e   = g_topi[i];
    se[tid] = e;
    __syncthreads();
    int r = 0;
    for (int j = 0; j < tid; j++) r += (se[j] == e);
    int loc = g_boff[blockIdx.x * NEXP + e] + r;
    g_slot[i] = (loc < CAP) ? (e * CAP + loc) : -1;
}

// ---------------- scatter with fp16 hi/lo split ----------------
__global__ void scatter_split(const float* __restrict__ x) {
    int i = blockIdx.x;
    int s = g_slot[i];
    if (s < 0) return;
    int t = i >> 1;
    int tid = threadIdx.x;                        // 128 threads, 8 floats each
    const float* src = x + (size_t)t * DDIM + tid * 8;
    float v[8];
    *(float4*)(v)     = *(const float4*)(src);
    *(float4*)(v + 4) = *(const float4*)(src + 4);
    unsigned short h[8], l[8];
#pragma unroll
    for (int j = 0; j < 8; j++) split1(v[j], h[j], l[j]);
    ((uint4*)(g_xe_hi + (size_t)s * DDIM))[tid] = *(const uint4*)h;
    ((uint4*)(g_xe_lo + (size_t)s * DDIM))[tid] = *(const uint4*)l;
}

// ---------------- weight transpose: [E,R,C] fp32 -> [E,C,R] fp16 (single copy) ---------
// Outputs referenced as __device__ globals from device code (R13 fix: host-side
// symbol args land in host memory via ATS).
// WHICH=1: w1 [E,D,F] -> g_wt1 [E,F,D];  WHICH=2: w2 [E,F,D] -> g_wt2 [E,D,F]
template <int R, int Cc, int WHICH>
__global__ void transpose_half(const float* __restrict__ in) {
    __half* oh = (WHICH == 1) ? g_wt1 : g_wt2;
    __shared__ float tile[32][33];
    int c0 = blockIdx.x * 32, r0 = blockIdx.y * 32, e = blockIdx.z;
    int tx = threadIdx.x, ty = threadIdx.y;
    const float* ip = in + (size_t)e * R * Cc;
#pragma unroll
    for (int i = 0; i < 4; i++)
        tile[ty + 8 * i][tx] = ip[(size_t)(r0 + ty + 8 * i) * Cc + c0 + tx];
    __syncthreads();
    size_t ob = (size_t)e * R * Cc;
#pragma unroll
    for (int i = 0; i < 4; i++) {
        float v = tile[tx][ty + 8 * i];
        size_t o = ob + (size_t)(c0 + ty + 8 * i) * R + r0 + tx;
        oh[o] = __float2half_rn(v);
    }
}

// ---------------- gelu (tanh approx, JAX default) ----------------
__device__ __forceinline__ float gelu_f(float v) {
    float u = 0.7978845608028654f * (v + 0.044715f * v * v * v);
    return 0.5f * v * (1.0f + tanhf(u));
}

// ---------------- tensor-core GEMM, fp16 2-term split ------------------------------------
// A split exactly (ah + al fp16), B rounded once to fp16:
//   D = ah*B + al*B   (error ~2^-12/sqrt(3) per layer from B rounding)
// MODE 0: h  = gelu(xe @ w1 + b1) -> h hi/lo fp16   (KDIM=1024, NTOT=4096)
// MODE 1: ye =       h @ w2 + b2  -> ye fp32        (KDIM=4096, NTOT=1024)
// 3-stage cp.async pipeline, 72KB dynamic smem, 2 CTAs/SM.
template <int KDIM, int NTOT, int MODE>
__global__ __launch_bounds__(256, 2)
void mma_gemm(const float* __restrict__ bias) {
    int e   = blockIdx.z;
    int cnt = min(g_count[e], CAP);
    int m0  = blockIdx.y * BM;
    if (m0 >= cnt) return;
    int n0  = blockIdx.x * BN;

    extern __shared__ __align__(16) char sm[];
    uint32_t smb = smem_u32(sm);

    const __half *Ah, *Al, *B;
    if (MODE == 0) { Ah = g_xe_hi; Al = g_xe_lo; B = g_wt1; }
    else           { Ah = g_h_hi;  Al = g_h_lo;  B = g_wt2; }

    size_t aBase = (size_t)e * CAP  * KDIM + (size_t)m0 * KDIM;
    size_t bBase = (size_t)e * NTOT * KDIM + (size_t)n0 * KDIM;

    int tid  = threadIdx.x;
    int lane = tid & 31;
    int wid  = tid >> 5;
    int wm   = (wid & 3) * 32;     // warp M offset (4 warps in M)
    int wn   = (wid >> 2) * 64;    // warp N offset (2 warps in N)

    // ---- loader mapping: thread -> rows (r0, r0+64), 16B col c0 ----
    int r0 = tid >> 2, c0 = tid & 3;
    int r1 = r0 + 64;
    uint32_t swz0 = (uint32_t)(r0 * 64 + ((c0 ^ ((r0 >> 1) & 3)) << 4));
    uint32_t swz1 = (uint32_t)(r1 * 64 + ((c0 ^ ((r1 >> 1) & 3)) << 4));
    size_t goff0 = (size_t)r0 * KDIM + c0 * 8;
    size_t goff1 = (size_t)r1 * KDIM + c0 * 8;

    // ---- per-lane ldmatrix offsets (ks=0); ks=1 XORs byte 32 -> k+16 ----
    int gq = lane >> 3;
    int ri = lane & 7;
    int a_r = ri + ((gq & 1) << 3);
    int a_c = (gq >> 1);
    uint32_t aoff[2];
#pragma unroll
    for (int mt = 0; mt < 2; mt++) {
        int m = wm + mt * 16 + a_r;
        aoff[mt] = (uint32_t)(m * 64 + ((a_c ^ ((m >> 1) & 3)) << 4));
    }
    int b_r = ri + ((gq >> 1) << 3);
    int b_c = (gq & 1);
    uint32_t boff[4];
#pragma unroll
    for (int bt = 0; bt < 4; bt++) {
        int n = wn + bt * 16 + b_r;
        boff[bt] = (uint32_t)(n * 64 + ((b_c ^ ((n >> 1) & 3)) << 4));
    }

    constexpr int KCH = KDIM / BK;

    auto issue_load = [&](int t, int buf) {
        int k0 = t * BK;
        uint32_t st = smb + buf * STAGE_SZ;
        const __half* pAh = Ah + aBase + k0;
        const __half* pAl = Al + aBase + k0;
        const __half* pB  = B  + bBase + k0;
        cp_async16(st + OFF_AH + swz0, pAh + goff0);
        cp_async16(st + OFF_AH + swz1, pAh + goff1);
        cp_async16(st + OFF_AL + swz0, pAl + goff0);
        cp_async16(st + OFF_AL + swz1, pAl + goff1);
        cp_async16(st + OFF_B  + swz0, pB + goff0);
        cp_async16(st + OFF_B  + swz1, pB + goff1);
    };

    float acc[2][8][4];
#pragma unroll
    for (int mt = 0; mt < 2; mt++)
#pragma unroll
        for (int nt = 0; nt < 8; nt++)
#pragma unroll
            for (int q = 0; q < 4; q++) acc[mt][nt][q] = 0.f;

    // ---- prologue: stages 0,1 in flight ----
    issue_load(0, 0); CP_COMMIT();
    issue_load(1, 1); CP_COMMIT();

    int buf = 0;
    for (int t = 0; t < KCH; t++) {
        CP_WAIT_1();                   // group for stage t complete
        __syncthreads();               // visible to all; prior readers done with this buffer

        int tn = t + 2;
        int nbuf = buf + 2; if (nbuf >= STAGES) nbuf -= STAGES;
        if (tn < KCH) { issue_load(tn, nbuf); CP_COMMIT(); }

        uint32_t st = smb + buf * STAGE_SZ;
#pragma unroll
        for (int ks = 0; ks < 2; ks++) {
            uint32_t kx = ks << 5;
            uint32_t ah[2][4], al[2][4];
            ldsm_x4(ah[0][0], ah[0][1], ah[0][2], ah[0][3], st + OFF_AH + (aoff[0] ^ kx));
            ldsm_x4(ah[1][0], ah[1][1], ah[1][2], ah[1][3], st + OFF_AH + (aoff[1] ^ kx));
            ldsm_x4(al[0][0], al[0][1], al[0][2], al[0][3], st + OFF_AL + (aoff[0] ^ kx));
            ldsm_x4(al[1][0], al[1][1], al[1][2], al[1][3], st + OFF_AL + (aoff[1] ^ kx));
            uint32_t b[4][4];
#pragma unroll
            for (int bt = 0; bt < 4; bt++)
                ldsm_x4(b[bt][0], b[bt][1], b[bt][2], b[bt][3], st + OFF_B + (boff[bt] ^ kx));
#pragma unroll
            for (int mt = 0; mt < 2; mt++)
#pragma unroll
                for (int nt = 0; nt < 8; nt++) {
                    mma16816(acc[mt][nt], ah[mt], &b[nt >> 1][(nt & 1) * 2]);
                    mma16816(acc[mt][nt], al[mt], &b[nt >> 1][(nt & 1) * 2]);
                }
        }
        if (++buf == STAGES) buf = 0;
    }

    // ---- epilogue ----
    int lrow = lane >> 2;
    int lcol = (lane & 3) * 2;
#pragma unroll
    for (int mt = 0; mt < 2; mt++) {
#pragma unroll
        for (int hh = 0; hh < 2; hh++) {
            int m = m0 + wm + mt * 16 + lrow + 8 * hh;
            size_t rb = ((size_t)e * CAP + m) * (size_t)NTOT;
#pragma unroll
            for (int nt = 0; nt < 8; nt++) {
                int cg = n0 + wn + nt * 8 + lcol;
                float2 bv = *(const float2*)(bias + (size_t)e * NTOT + cg);
                float v0 = acc[mt][nt][2 * hh]     + bv.x;
                float v1 = acc[mt][nt][2 * hh + 1] + bv.y;
                if (MODE == 0) {
                    v0 = gelu_f(v0);
                    v1 = gelu_f(v1);
                    unsigned short h0, l0, h1, l1;
                    split1(v0, h0, l0);
                    split1(v1, h1, l1);
                    *(uint32_t*)(g_h_hi + rb + cg) = (uint32_t)h0 | ((uint32_t)h1 << 16);
                    *(uint32_t*)(g_h_lo + rb + cg) = (uint32_t)l0 | ((uint32_t)l1 << 16);
                } else {
                    float2 o; o.x = v0; o.y = v1;
                    *(float2*)(g_ye + rb + cg) = o;
                }
            }
        }
    }
}

// ---------------- combine: gate-weighted sum over K=2 slots ----------------
__global__ void combine_kernel(float* __restrict__ out) {
    int t   = blockIdx.x;
    int tid = threadIdx.x;
    int   s0 = g_slot[2 * t];
    int   s1 = g_slot[2 * t + 1];
    float w0 = g_topv[2 * t];
    float w1 = g_topv[2 * t + 1];
    float4 r = make_float4(0.f, 0.f, 0.f, 0.f);
    if (s0 >= 0) {
        float4 y = *(const float4*)(g_ye + (size_t)s0 * DDIM + tid * 4);
        r.x += w0 * y.x; r.y += w0 * y.y; r.z += w0 * y.z; r.w += w0 * y.w;
    }
    if (s1 >= 0) {
        float4 y = *(const float4*)(g_ye + (size_t)s1 * DDIM + tid * 4);
        r.x += w1 * y.x; r.y += w1 * y.y; r.z += w1 * y.z; r.w += w1 * y.w;
    }
    *(float4*)(out + (size_t)t * DDIM + tid * 4) = r;
}

// ---------------- launch ----------------
extern "C" void kernel_launch(void* const* d_in, const int* in_sizes, int n_in,
                              void* d_out, int out_size) {
    const float* x  = (const float*)d_in[0];
    const float* gw = (const float*)d_in[1];
    const float* w1 = (const float*)d_in[2];
    const float* b1 = (const float*)d_in[3];
    const float* w2 = (const float*)d_in[4];
    const float* b2 = (const float*)d_in[5];
    float* out = (float*)d_out;

    cudaFuncSetAttribute(mma_gemm<DDIM, FDIM, 0>,
                         cudaFuncAttributeMaxDynamicSharedMemorySize, GEMM_SMEM);
    cudaFuncSetAttribute(mma_gemm<FDIM, DDIM, 1>,
                         cudaFuncAttributeMaxDynamicSharedMemorySize, GEMM_SMEM);

    // weight prep: w1 [E,D,F] -> g_wt1 [E,F,D]; w2 [E,F,D] -> g_wt2 [E,D,F]
    transpose_half<DDIM, FDIM, 1><<<dim3(FDIM / 32, DDIM / 32, NEXP), dim3(32, 8)>>>(w1);
    transpose_half<FDIM, DDIM, 2><<<dim3(DDIM / 32, FDIM / 32, NEXP), dim3(32, 8)>>>(w2);

    gating_kernel<<<T_TOK / 8, 256>>>(x, gw);
    hist_kernel<<<NB, CHUNK>>>();
    scan_kernel<<<1, 32>>>();
    rank_kernel<<<NB, CHUNK>>>();
    scatter_split<<<NFLAT, 128>>>(x);

    mma_gemm<DDIM, FDIM, 0><<<dim3(FDIM / BN, CAP / BM, NEXP), 256, GEMM_SMEM>>>(b1);
    mma_gemm<FDIM, DDIM, 1><<<dim3(DDIM / BN, CAP / BM, NEXP), 256, GEMM_SMEM>>>(b2);

    combine_kernel<<<T_TOK, 256>>>(out);
}